// round 13
// baseline (speedup 1.0000x reference)
#include <cuda_runtime.h>
#include <cuda_bf16.h>
#include <math.h>
#include <stdint.h>

// ---------------------------------------------------------------------------
// Problem constants
// ---------------------------------------------------------------------------
#define Bc   4
#define Sq   2048
#define Dm   1024
#define Hh   16
#define Ee   8
#define Ff   4096
#define Ntok (Bc*Sq)          // 8192
#define CAP  1280
#define SLOTS (Ee*CAP)        // 10240

typedef __nv_bfloat16 bf16;
typedef __nv_bfloat162 bf162;

// ---------------------------------------------------------------------------
// Device scratch
// ---------------------------------------------------------------------------
__device__ bf16  g_xln [Ntok*Dm];
__device__ bf16  g_qkv [Ntok*3*Dm];
__device__ bf16  g_attn[Ntok*Dm];
__device__ bf16  g_x2b [Ntok*Dm];
__device__ bf16  g_hbuf[(size_t)SLOTS*Ff];
__device__ float g_probs[Ntok*Ee];
__device__ float g_zterm[Ntok];
__device__ float g_gate [Ntok];
__device__ int   g_eidx [Ntok];
__device__ int   g_tok  [SLOTS];
__device__ int   g_cnt  [Ee];
// bf16 weight copies / transposes ([N,K] layouts)
__device__ bf16 g_ipw16[3*Dm*Dm];
__device__ bf16 g_opw16[Dm*Dm];
__device__ bf16 g_w1t [(size_t)Ee*Ff*Dm];   // [E][F][D]
__device__ bf16 g_w2t [(size_t)Ee*Dm*Ff];   // [E][D][F]

// ---------------------------------------------------------------------------
// Helpers
// ---------------------------------------------------------------------------
__device__ __forceinline__ uint32_t smem_u32(const void* p) {
    uint32_t a;
    asm("{ .reg .u64 t; cvta.to.shared.u64 t, %1; cvt.u32.u64 %0, t; }"
        : "=r"(a) : "l"(p));
    return a;
}
__device__ __forceinline__ void cp16(uint32_t dst, const void* src) {
    asm volatile("cp.async.cg.shared.global [%0], [%1], 16;" :: "r"(dst), "l"(src));
}
__device__ __forceinline__ void cp16z(uint32_t dst, const void* src, uint32_t sz) {
    asm volatile("cp.async.cg.shared.global [%0], [%1], 16, %2;"
                 :: "r"(dst), "l"(src), "r"(sz));
}
__device__ __forceinline__ void ldm_x4(uint32_t* r, uint32_t addr) {
    asm volatile("ldmatrix.sync.aligned.m8n8.x4.shared.b16 {%0,%1,%2,%3}, [%4];"
        : "=r"(r[0]), "=r"(r[1]), "=r"(r[2]), "=r"(r[3]) : "r"(addr));
}
__device__ __forceinline__ void ldm_x4t(uint32_t* r, uint32_t addr) {
    asm volatile("ldmatrix.sync.aligned.m8n8.x4.trans.shared.b16 {%0,%1,%2,%3}, [%4];"
        : "=r"(r[0]), "=r"(r[1]), "=r"(r[2]), "=r"(r[3]) : "r"(addr));
}
__device__ __forceinline__ void mma_bf16(float* d, const uint32_t* a,
                                         uint32_t b0, uint32_t b1) {
    asm volatile(
        "mma.sync.aligned.m16n8k16.row.col.f32.bf16.bf16.f32 "
        "{%0,%1,%2,%3}, {%4,%5,%6,%7}, {%8,%9}, {%0,%1,%2,%3};"
        : "+f"(d[0]), "+f"(d[1]), "+f"(d[2]), "+f"(d[3])
        : "r"(a[0]), "r"(a[1]), "r"(a[2]), "r"(a[3]), "r"(b0), "r"(b1));
}
__device__ __forceinline__ uint32_t pack_bf(float lo, float hi) {
    bf162 v = __float22bfloat162_rn(make_float2(lo, hi));
    return *(uint32_t*)&v;
}
// fast exp via exp2 polynomial on the FMA pipe (MUFU is slow on B300)
__device__ __forceinline__ float expp(float x) {
    float y = fmaxf(x * 1.4426950408889634f, -120.f);
    float t = y + 12582912.f;
    int   e = __float_as_int(t);
    float r = t - 12582912.f;
    float f = y - r;
    float p = 1.3333558146e-3f;
    p = fmaf(p, f, 9.6181291076e-3f);
    p = fmaf(p, f, 5.5504108664e-2f);
    p = fmaf(p, f, 2.4022650696e-1f);
    p = fmaf(p, f, 6.9314718056e-1f);
    p = fmaf(p, f, 1.0f);
    float sc = __int_as_float((e - 0x4b400000 + 127) << 23);
    return p * sc;
}

__device__ __forceinline__ void store_pair(float* C, size_t off, float v0, float v1) {
    *(float2*)(C + off) = make_float2(v0, v1);
}
__device__ __forceinline__ void store_pair(bf16* C, size_t off, float v0, float v1) {
    *(bf162*)(C + off) = __float22bfloat162_rn(make_float2(v0, v1));
}

// ---------------------------------------------------------------------------
// bf16 mma GEMM: C[M,N] = A[M,K] @ B[N,K]^T (+bias, relu, residual)
// 128x256 block tile, 128-half k-chunk (272B padded rows), 2-stage double
// buffer, 8 warps (2m x 4n), warp tile 64x64. ONE __syncthreads per k-chunk.
// All 8 ldmatrix of a kk batched ahead of the 32 mma (latency hiding).
// ---------------------------------------------------------------------------
#define BM 128
#define BN 256
#define KCH 128
#define RSTR 272                     // 256B data + 16B pad
#define STAGE_B ((BM+BN)*RSTR)       // 104448 bytes
#define GEMM_SMEM (2*STAGE_B + 512)  // 209408

template<typename TO, bool RELU, bool RES, bool GATHER, bool SCATTER>
__global__ __launch_bounds__(256, 1) void gemm_mma(
    const bf16* __restrict__ A, const bf16* __restrict__ Bm,
    const float* __restrict__ bias, const float* __restrict__ Res,
    TO* __restrict__ C, int Nld, int K,
    int rowsPerExpert, long long bExpStride, int biasExpStride,
    const int* __restrict__ tokIdx, const float* __restrict__ gate)
{
    extern __shared__ char smem[];
    const uint32_t sb0 = smem_u32(smem);
    int* stok = (int*)(smem + 2*STAGE_B);
    const int tid = threadIdx.x;
    const int wid = tid >> 5, lane = tid & 31;
    const int j8 = lane & 7, gi = lane >> 3;
    const int lr = lane >> 2, lc = lane & 3;
    const int row0 = blockIdx.y * BM, col0 = blockIdx.x * BN;
    const int expert = row0 / rowsPerExpert;
    const bf16* Bexp = Bm + (long long)expert * bExpStride;
    const float* bb  = bias + (long long)expert * biasExpStride;
    const int m0 = (wid & 1) * 64, n0 = (wid >> 1) * 64;

    const bf16* Abase = GATHER ? A : A + (size_t)row0 * K;
    const bf16* Bbase = Bexp + (size_t)col0 * K;

    if (GATHER || SCATTER) {
        int v = 0;
        if (tid < BM) {
            int t = tokIdx[row0 + tid];
            stok[tid] = t;
            v = (t >= 0);
        }
        if (!__syncthreads_or(v)) return;   // whole tile empty -> no effect
    }

    const int arow = j8 + (gi & 1) * 8;
    const int aoff = (gi >> 1) * 16;
    const int brow = j8 + (gi >> 1) * 8;
    const int boff = (gi & 1) * 16;

    float acc[4][8][4];
#pragma unroll
    for (int mt = 0; mt < 4; mt++)
#pragma unroll
        for (int t = 0; t < 8; t++)
#pragma unroll
            for (int q = 0; q < 4; q++) acc[mt][t][q] = 0.f;

    const int nch = K / KCH;

    auto load_stage = [&](int s, int ch) {
        const uint32_t sa  = sb0 + (uint32_t)s * STAGE_B;
        const uint32_t sbm = sa + BM * RSTR;
        const bf16* Bcp = Bbase + ch * KCH;
#pragma unroll
        for (int q = 0; q < 8; q++) {          // A: 2048 segs of 16B
            int seg = tid + 256 * q;
            int r = seg >> 4, c = seg & 15;
            if (GATHER) {
                int t = stok[r];
                uint32_t sz = (t >= 0) ? 16u : 0u;
                const bf16* srcp = Abase + (size_t)(t >= 0 ? t : 0) * K + ch * KCH + c * 8;
                cp16z(sa + (uint32_t)(r * RSTR + c * 16), srcp, sz);
            } else {
                cp16(sa + (uint32_t)(r * RSTR + c * 16),
                     Abase + (size_t)r * K + ch * KCH + c * 8);
            }
        }
#pragma unroll
        for (int q = 0; q < 16; q++) {         // B: 4096 segs of 16B
            int seg = tid + 256 * q;
            int r = seg >> 4, c = seg & 15;
            cp16(sbm + (uint32_t)(r * RSTR + c * 16), Bcp + (size_t)r * K + c * 8);
        }
    };

    load_stage(0, 0);
    asm volatile("cp.async.commit_group;");

    for (int i = 0; i < nch; i++) {
        asm volatile("cp.async.wait_group 0;");
        __syncthreads();
        if (i + 1 < nch) load_stage((i + 1) & 1, i + 1);
        asm volatile("cp.async.commit_group;");

        const uint32_t sa  = sb0 + (uint32_t)(i & 1) * STAGE_B;
        const uint32_t sbm = sa + BM * RSTR;
#pragma unroll
        for (int kk = 0; kk < KCH/16; kk++) {
            uint32_t af[4][4], bfr[4][4];
#pragma unroll
            for (int mt = 0; mt < 4; mt++)
                ldm_x4(af[mt], sa + (uint32_t)((m0 + mt * 16 + arow) * RSTR + kk * 32 + aoff));
#pragma unroll
            for (int nt = 0; nt < 4; nt++)
                ldm_x4(bfr[nt], sbm + (uint32_t)((n0 + nt * 16 + brow) * RSTR + kk * 32 + boff));
#pragma unroll
            for (int nt = 0; nt < 4; nt++)
#pragma unroll
                for (int mt = 0; mt < 4; mt++) {
                    mma_bf16(acc[mt][nt * 2 + 0], af[mt], bfr[nt][0], bfr[nt][1]);
                    mma_bf16(acc[mt][nt * 2 + 1], af[mt], bfr[nt][2], bfr[nt][3]);
                }
        }
    }

    // epilogue
#pragma unroll
    for (int mt = 0; mt < 4; mt++) {
        const int gr = row0 + m0 + mt * 16 + lr;
        int t0 = 0, t1 = 0;
        float g0 = 0.f, g1 = 0.f;
        if (SCATTER) {
            t0 = stok[m0 + mt * 16 + lr]; t1 = stok[m0 + mt * 16 + lr + 8];
            g0 = (t0 >= 0) ? gate[t0] : 0.f;
            g1 = (t1 >= 0) ? gate[t1] : 0.f;
        }
#pragma unroll
        for (int nt = 0; nt < 4; nt++) {
#pragma unroll
            for (int pr = 0; pr < 2; pr++) {
                const int gc = col0 + n0 + nt * 16 + pr * 8 + lc * 2;
                float* d = acc[mt][nt * 2 + pr];
                float b0 = bb[gc], b1 = bb[gc + 1];
                float v0 = d[0] + b0, v1 = d[1] + b1;
                float v2 = d[2] + b0, v3 = d[3] + b1;
                if (RELU) {
                    v0 = fmaxf(v0, 0.f); v1 = fmaxf(v1, 0.f);
                    v2 = fmaxf(v2, 0.f); v3 = fmaxf(v3, 0.f);
                }
                if (RES) {
                    float2 r0 = *(const float2*)(Res + (size_t)gr * Nld + gc);
                    float2 r1 = *(const float2*)(Res + (size_t)(gr + 8) * Nld + gc);
                    v0 += r0.x; v1 += r0.y; v2 += r1.x; v3 += r1.y;
                }
                if (SCATTER) {
                    if (t0 >= 0) {
                        float2 cur = *(float2*)((float*)C + (size_t)t0 * Nld + gc);
                        *(float2*)((float*)C + (size_t)t0 * Nld + gc) =
                            make_float2(cur.x + g0 * v0, cur.y + g0 * v1);
                    }
                    if (t1 >= 0) {
                        float2 cur = *(float2*)((float*)C + (size_t)t1 * Nld + gc);
                        *(float2*)((float*)C + (size_t)t1 * Nld + gc) =
                            make_float2(cur.x + g1 * v2, cur.y + g1 * v3);
                    }
                } else {
                    store_pair(C, (size_t)gr * Nld + gc, v0, v1);
                    store_pair(C, (size_t)(gr + 8) * Nld + gc, v2, v3);
                }
            }
        }
    }
}

// ---------------------------------------------------------------------------
// Flash attention, bf16 mma. 256 threads (8 warps), q-tile 128, k-tiles of
// 128 (processed as two sequential 64-col softmax halves -> identical math),
// double-buffered. ONE __syncthreads per 128-row k-tile.
// ---------------------------------------------------------------------------
#define ATS 18432                     // one 128x144B tile
#define AT_SMEM (ATS + 4*ATS + 1024 + 256)

__global__ __launch_bounds__(256) void attn_mma(
    const bf16* __restrict__ qkv,
    const unsigned char* __restrict__ pad,
    bf16* __restrict__ outp)
{
    extern __shared__ char smem[];
    const uint32_t sQ  = smem_u32(smem);
    const uint32_t sK0 = sQ + ATS;
    const uint32_t sV0 = sK0 + 2*ATS;
    float* mkp = (float*)(smem + ATS + 4*ATS);   // 2 stages x 128 floats

    const int tid = threadIdx.x;
    const int wid = tid >> 5, lane = tid & 31;
    const int j8 = lane & 7, gi = lane >> 3;
    const int lc = lane & 3, lr = lane >> 2;
    const int bh = blockIdx.y, b = bh >> 4, h = bh & 15;
    const int q0 = blockIdx.x * 128;
    const size_t tokBase = (size_t)b * Sq;

    {
        const bf16* qb = qkv + (tokBase + q0) * 3072 + h * 64;
#pragma unroll
        for (int q = 0; q < 4; q++) {
            int seg = tid + 256 * q;
            int r = seg >> 3, c = seg & 7;
            cp16(sQ + (uint32_t)(r * 144 + c * 16), qb + (size_t)r * 3072 + c * 8);
        }
    }
    asm volatile("cp.async.commit_group;");

    auto prefetch = [&](int st, int kt) {       // loads 128 K rows + 128 V rows
        const int k0 = kt * 128;
        const bf16* kb = qkv + (tokBase + k0) * 3072 + 1024 + h * 64;
        const bf16* vb = qkv + (tokBase + k0) * 3072 + 2048 + h * 64;
        const uint32_t sk = sK0 + (uint32_t)st * ATS, sv = sV0 + (uint32_t)st * ATS;
#pragma unroll
        for (int q = 0; q < 4; q++) {
            int seg = tid + 256 * q;
            int r = seg >> 3, c = seg & 7;
            cp16(sk + (uint32_t)(r * 144 + c * 16), kb + (size_t)r * 3072 + c * 8);
            cp16(sv + (uint32_t)(r * 144 + c * 16), vb + (size_t)r * 3072 + c * 8);
        }
        if (tid < 128) mkp[st * 128 + tid] = pad[tokBase + k0 + tid] ? -1e9f : 0.f;
    };

    prefetch(0, 0);
    asm volatile("cp.async.commit_group;");
    asm volatile("cp.async.wait_group 1;");   // Q resident
    __syncthreads();

    const int arow = j8 + (gi & 1) * 8, aoff = (gi >> 1) * 16;
    const int brow = j8 + (gi >> 1) * 8, boff = (gi & 1) * 16;

    uint32_t qa[4][4];
#pragma unroll
    for (int kd = 0; kd < 4; kd++)
        ldm_x4(qa[kd], sQ + (uint32_t)((wid * 16 + arow) * 144 + kd * 32 + aoff));

    float m0v = -1e30f, m1v = -1e30f, l0 = 0.f, l1 = 0.f;
    float o[8][4];
#pragma unroll
    for (int dt = 0; dt < 8; dt++)
#pragma unroll
        for (int q = 0; q < 4; q++) o[dt][q] = 0.f;

    for (int kt = 0; kt < Sq / 128; kt++) {
        const int st = kt & 1;
        asm volatile("cp.async.wait_group 0;");
        __syncthreads();
        if (kt + 1 < Sq / 128) prefetch(st ^ 1, kt + 1);
        asm volatile("cp.async.commit_group;");

        const uint32_t sk = sK0 + (uint32_t)st * ATS, sv = sV0 + (uint32_t)st * ATS;

#pragma unroll
        for (int hf = 0; hf < 2; hf++) {        // two 64-col softmax halves
            const int hb64 = hf * 64;
            float s[8][4];
#pragma unroll
            for (int j = 0; j < 8; j++)
#pragma unroll
                for (int q = 0; q < 4; q++) s[j][q] = 0.f;

#pragma unroll
            for (int jp = 0; jp < 4; jp++) {
#pragma unroll
                for (int kd = 0; kd < 4; kd++) {
                    uint32_t bfr[4];
                    ldm_x4(bfr, sk + (uint32_t)((hb64 + jp * 16 + brow) * 144 + kd * 32 + boff));
                    mma_bf16(s[2 * jp],     qa[kd], bfr[0], bfr[1]);
                    mma_bf16(s[2 * jp + 1], qa[kd], bfr[2], bfr[3]);
                }
            }

            float rmax0 = -1e30f, rmax1 = -1e30f;
#pragma unroll
            for (int j = 0; j < 8; j++) {
                float mka = mkp[st * 128 + hb64 + j * 8 + 2 * lc];
                float mkb = mkp[st * 128 + hb64 + j * 8 + 2 * lc + 1];
                s[j][0] = fmaf(s[j][0], 0.125f, mka);
                s[j][1] = fmaf(s[j][1], 0.125f, mkb);
                s[j][2] = fmaf(s[j][2], 0.125f, mka);
                s[j][3] = fmaf(s[j][3], 0.125f, mkb);
                rmax0 = fmaxf(rmax0, fmaxf(s[j][0], s[j][1]));
                rmax1 = fmaxf(rmax1, fmaxf(s[j][2], s[j][3]));
            }
            rmax0 = fmaxf(rmax0, __shfl_xor_sync(0xffffffffu, rmax0, 1));
            rmax0 = fmaxf(rmax0, __shfl_xor_sync(0xffffffffu, rmax0, 2));
            rmax1 = fmaxf(rmax1, __shfl_xor_sync(0xffffffffu, rmax1, 1));
            rmax1 = fmaxf(rmax1, __shfl_xor_sync(0xffffffffu, rmax1, 2));
            float nm0 = fmaxf(m0v, rmax0), nm1 = fmaxf(m1v, rmax1);
            float c0 = expp(m0v - nm0), c1 = expp(m1v - nm1);
            m0v = nm0; m1v = nm1;
            float rs0 = 0.f, rs1 = 0.f;
#pragma unroll
            for (int j = 0; j < 8; j++) {
                s[j][0] = expp(s[j][0] - nm0); s[j][1] = expp(s[j][1] - nm0);
                s[j][2] = expp(s[j][2] - nm1); s[j][3] = expp(s[j][3] - nm1);
                rs0 += s[j][0] + s[j][1];
                rs1 += s[j][2] + s[j][3];
            }
            rs0 += __shfl_xor_sync(0xffffffffu, rs0, 1);
            rs0 += __shfl_xor_sync(0xffffffffu, rs0, 2);
            rs1 += __shfl_xor_sync(0xffffffffu, rs1, 1);
            rs1 += __shfl_xor_sync(0xffffffffu, rs1, 2);
            l0 = l0 * c0 + rs0; l1 = l1 * c1 + rs1;
#pragma unroll
            for (int dt = 0; dt < 8; dt++) {
                o[dt][0] *= c0; o[dt][1] *= c0; o[dt][2] *= c1; o[dt][3] *= c1;
            }

            uint32_t pa[4][4];
#pragma unroll
            for (int t = 0; t < 4; t++) {
                pa[t][0] = pack_bf(s[2 * t][0],     s[2 * t][1]);
                pa[t][1] = pack_bf(s[2 * t][2],     s[2 * t][3]);
                pa[t][2] = pack_bf(s[2 * t + 1][0], s[2 * t + 1][1]);
                pa[t][3] = pack_bf(s[2 * t + 1][2], s[2 * t + 1][3]);
            }
#pragma unroll
            for (int t = 0; t < 4; t++) {
#pragma unroll
                for (int dp = 0; dp < 4; dp++) {
                    uint32_t vf[4];
                    ldm_x4t(vf, sv + (uint32_t)((hb64 + t * 16 + arow) * 144 + dp * 32 + aoff));
                    mma_bf16(o[2 * dp],     pa[t], vf[0], vf[1]);
                    mma_bf16(o[2 * dp + 1], pa[t], vf[2], vf[3]);
                }
            }
        }
    }

    float inv0 = 1.f / l0, inv1 = 1.f / l1;
    const int rg = q0 + wid * 16 + lr;
    bf16* ob = outp + (tokBase + rg) * Dm + h * 64;
#pragma unroll
    for (int dt = 0; dt < 8; dt++) {
        *(bf162*)(ob + dt * 8 + 2 * lc) =
            __float22bfloat162_rn(make_float2(o[dt][0] * inv0, o[dt][1] * inv0));
        *(bf162*)(ob + (size_t)8 * Dm + dt * 8 + 2 * lc) =
            __float22bfloat162_rn(make_float2(o[dt][2] * inv1, o[dt][3] * inv1));
    }
}

// ---------------------------------------------------------------------------
// LayerNorm (bf16 out, for LN1)
// ---------------------------------------------------------------------------
__global__ __launch_bounds__(256) void ln_kernel(const float* __restrict__ in,
                                                 const float* __restrict__ g,
                                                 const float* __restrict__ b,
                                                 bf16* __restrict__ out)
{
    int n = blockIdx.x, tid = threadIdx.x;
    float4 v = ((const float4*)(in + (size_t)n*Dm))[tid];
    float s  = v.x+v.y+v.z+v.w;
    float s2 = v.x*v.x+v.y*v.y+v.z*v.z+v.w*v.w;
    __shared__ float r1[256], r2[256];
    r1[tid]=s; r2[tid]=s2; __syncthreads();
    for (int st=128; st; st>>=1) {
        if (tid<st) { r1[tid]+=r1[tid+st]; r2[tid]+=r2[tid+st]; }
        __syncthreads();
    }
    float mean = r1[0]*(1.0f/Dm);
    float var  = r2[0]*(1.0f/Dm) - mean*mean;
    float rstd = rsqrtf(var + 1e-5f);
    float4 gg = ((const float4*)g)[tid];
    float4 bb = ((const float4*)b)[tid];
    float o0 = (v.x-mean)*rstd*gg.x + bb.x;
    float o1 = (v.y-mean)*rstd*gg.y + bb.y;
    float o2 = (v.z-mean)*rstd*gg.z + bb.z;
    float o3 = (v.w-mean)*rstd*gg.w + bb.w;
    size_t base = (size_t)n*Dm + tid*4;
    store_pair(out, base, o0, o1);
    store_pair(out, base + 2, o2, o3);
}

// ---------------------------------------------------------------------------
// LN2 + router fused (reads src1 values from `out` buffer)
// ---------------------------------------------------------------------------
__global__ __launch_bounds__(256) void ln2_router(const float* __restrict__ in,
                                                  const float* __restrict__ g,
                                                  const float* __restrict__ b,
                                                  bf16* __restrict__ outh,
                                                  const float* __restrict__ rw,
                                                  const float* __restrict__ rb,
                                                  const unsigned char* __restrict__ pad)
{
    int n = blockIdx.x, tid = threadIdx.x;
    __shared__ float r1[256], r2[256];
    __shared__ float xs[1024];
    __shared__ float lg[8];
    float4 v = ((const float4*)(in + (size_t)n*Dm))[tid];
    float s  = v.x+v.y+v.z+v.w;
    float s2 = v.x*v.x+v.y*v.y+v.z*v.z+v.w*v.w;
    r1[tid]=s; r2[tid]=s2; __syncthreads();
    for (int st=128; st; st>>=1) {
        if (tid<st) { r1[tid]+=r1[tid+st]; r2[tid]+=r2[tid+st]; }
        __syncthreads();
    }
    float mean = r1[0]*(1.0f/Dm);
    float var  = r2[0]*(1.0f/Dm) - mean*mean;
    float rstd = rsqrtf(var + 1e-5f);
    float4 gg = ((const float4*)g)[tid];
    float4 bb = ((const float4*)b)[tid];
    float4 o;
    o.x = (v.x-mean)*rstd*gg.x + bb.x;
    o.y = (v.y-mean)*rstd*gg.y + bb.y;
    o.z = (v.z-mean)*rstd*gg.z + bb.z;
    o.w = (v.w-mean)*rstd*gg.w + bb.w;
    bf162* hp = (bf162*)(outh + (size_t)n*Dm);
    hp[tid*2]   = __float22bfloat162_rn(make_float2(o.x, o.y));
    hp[tid*2+1] = __float22bfloat162_rn(make_float2(o.z, o.w));
    ((float4*)xs)[tid] = o;
    __syncthreads();
    int w = tid >> 5, lane = tid & 31;
    float acc = 0.f;
    for (int i = lane; i < 1024; i += 32) acc += xs[i] * rw[i*8 + w];
    for (int off=16; off; off>>=1) acc += __shfl_xor_sync(0xffffffffu, acc, off);
    if (lane == 0) lg[w] = acc + rb[w];
    __syncthreads();
    if (tid == 0) {
        float mx = lg[0]; int ei = 0;
        for (int e=1;e<8;e++) if (lg[e] > mx) { mx = lg[e]; ei = e; }
        float pr[8], se = 0.f;
        for (int e=0;e<8;e++) { pr[e] = expf(lg[e]-mx); se += pr[e]; }
        float inv = 1.f/se;
        bool valid = (pad[n] == 0);
        float tm = valid ? 1.f : 0.f;
        for (int e=0;e<8;e++) g_probs[n*8+e] = pr[e]*inv*tm;
        g_gate[n] = pr[ei]*inv;
        g_eidx[n] = ei;
        float lse = mx + logf(se);
        g_zterm[n] = lse*lse*tm;
    }
}

// ---------------------------------------------------------------------------
// Weight prep
// ---------------------------------------------------------------------------
__global__ __launch_bounds__(256) void bf16_copy(const float* __restrict__ in,
                                                 bf16* __restrict__ out, int n4)
{
    int i = blockIdx.x*256 + threadIdx.x;
    if (i < n4) {
        float4 v = ((const float4*)in)[i];
        ((bf162*)out)[i*2]   = __float22bfloat162_rn(make_float2(v.x, v.y));
        ((bf162*)out)[i*2+1] = __float22bfloat162_rn(make_float2(v.z, v.w));
    }
}

__global__ __launch_bounds__(256) void transpose_bf16(const float* __restrict__ in,
                                                      bf16* __restrict__ out,
                                                      int R, int Cc)
{
    __shared__ float t[32][33];
    int e = blockIdx.z;
    const float* ip = in  + (size_t)e*R*Cc;
    bf16* op        = out + (size_t)e*R*Cc;
    int c0 = blockIdx.x*32, r0 = blockIdx.y*32;
    int tx = threadIdx.x, ty = threadIdx.y;
#pragma unroll
    for (int j=0;j<32;j+=8)
        t[ty+j][tx] = ip[(size_t)(r0+ty+j)*Cc + c0+tx];
    __syncthreads();
#pragma unroll
    for (int j=0;j<32;j+=8)
        op[(size_t)(c0+ty+j)*R + r0+tx] = __float2bfloat16_rn(t[tx][ty+j]);
}

// ---------------------------------------------------------------------------
// Routing scan
// ---------------------------------------------------------------------------
__global__ __launch_bounds__(1024) void scan_kernel(const unsigned char* __restrict__ pad)
{
    __shared__ unsigned char sc[Ntok];
    __shared__ int base[8];
    int tid = threadIdx.x;
    for (int i = tid; i < SLOTS; i += 1024) g_tok[i] = -1;
    for (int i = tid; i < Ntok; i += 1024)
        sc[i] = (unsigned char)(g_eidx[i] | (pad[i] ? 0 : 16));
    if (tid < 8) base[tid] = 0;
    __syncthreads();
    if (tid < 32) {
        int lane = tid;
        for (int c = 0; c < Ntok/32; c++) {
            int i = c*32 + lane;
            int code = sc[i];
            int e = code & 7;
            bool valid = (code & 16) != 0;
            unsigned peers = __match_any_sync(0xffffffffu, e);
            unsigned vmask = __ballot_sync(0xffffffffu, valid);
            unsigned pv = peers & vmask;
            int myrank = __popc(pv & ((1u << lane) - 1u));
            int b0 = base[e];
            __syncwarp();
            int pos = b0 + myrank;
            bool keep = valid && (pos < CAP);
            if (keep) g_tok[e*CAP + pos] = i;
            if (valid && lane == (__ffs(pv) - 1)) base[e] = b0 + __popc(pv);
            __syncwarp();
        }
        if (lane < 8) g_cnt[lane] = base[lane];
    }
}

// ---------------------------------------------------------------------------
// Loss reduction
// ---------------------------------------------------------------------------
__global__ __launch_bounds__(256) void loss_kernel(const unsigned char* __restrict__ pad,
                                                   float* __restrict__ out)
{
    int tid = threadIdx.x;
    float zs = 0.f, ps[8];
    int cnt = 0;
#pragma unroll
    for (int e=0;e<8;e++) ps[e]=0.f;
    for (int n = tid; n < Ntok; n += 256) {
        if (pad[n] == 0) cnt++;
        zs += g_zterm[n];
#pragma unroll
        for (int e=0;e<8;e++) ps[e] += g_probs[n*8+e];
    }
    __shared__ float red[256];
    __shared__ float res[10];
    float vals[10];
    vals[0] = (float)cnt; vals[1] = zs;
    for (int e=0;e<8;e++) vals[2+e] = ps[e];
    for (int q=0;q<10;q++) {
        red[tid] = vals[q]; __syncthreads();
        for (int st=128; st; st>>=1) {
            if (tid < st) red[tid] += red[tid+st];
            __syncthreads();
        }
        if (tid == 0) res[q] = red[0];
        __syncthreads();
    }
    if (tid == 0) {
        float denom = fmaxf(res[0], 1.f);
        float lb = 0.f;
        for (int e=0;e<8;e++) lb += ((float)g_cnt[e]/denom) * (res[2+e]/denom);
        lb *= (float)Ee;
        out[(size_t)Ntok*Dm]     = lb;
        out[(size_t)Ntok*Dm + 1] = res[1]/denom;
    }
}

// ---------------------------------------------------------------------------
// Launch
// ---------------------------------------------------------------------------
extern "C" void kernel_launch(void* const* d_in, const int* in_sizes, int n_in,
                              void* d_out, int out_size)
{
    const float* src  = (const float*)d_in[0];
    const unsigned char* pad = (const unsigned char*)d_in[1];
    const float* ln1g = (const float*)d_in[2];
    const float* ln1b = (const float*)d_in[3];
    const float* ipw  = (const float*)d_in[4];
    const float* ipb  = (const float*)d_in[5];
    const float* opw  = (const float*)d_in[6];
    const float* opb  = (const float*)d_in[7];
    const float* ln2g = (const float*)d_in[8];
    const float* ln2b = (const float*)d_in[9];
    const float* rw   = (const float*)d_in[10];
    const float* rb   = (const float*)d_in[11];
    const float* w1   = (const float*)d_in[12];
    const float* b1   = (const float*)d_in[13];
    const float* w2   = (const float*)d_in[14];
    const float* b2   = (const float*)d_in[15];
    float* out = (float*)d_out;

    bf16 *xln, *qkv, *attn, *x2b, *hb, *ipw16, *opw16, *w1t, *w2t;
    float *gate;
    int *tok;
    cudaGetSymbolAddress((void**)&xln,  g_xln);
    cudaGetSymbolAddress((void**)&qkv,  g_qkv);
    cudaGetSymbolAddress((void**)&attn, g_attn);
    cudaGetSymbolAddress((void**)&x2b,  g_x2b);
    cudaGetSymbolAddress((void**)&hb,   g_hbuf);
    cudaGetSymbolAddress((void**)&ipw16, g_ipw16);
    cudaGetSymbolAddress((void**)&opw16, g_opw16);
    cudaGetSymbolAddress((void**)&w1t,  g_w1t);
    cudaGetSymbolAddress((void**)&w2t,  g_w2t);
    cudaGetSymbolAddress((void**)&tok,  g_tok);
    cudaGetSymbolAddress((void**)&gate, g_gate);

    static cudaStream_t s2 = nullptr;
    static cudaEvent_t ev0 = nullptr, evA = nullptr, ev1 = nullptr,
                       ev2 = nullptr, ev3 = nullptr;
    if (!s2) {
        cudaStreamCreateWithFlags(&s2, cudaStreamNonBlocking);
        cudaEventCreateWithFlags(&ev0, cudaEventDisableTiming);
        cudaEventCreateWithFlags(&evA, cudaEventDisableTiming);
        cudaEventCreateWithFlags(&ev1, cudaEventDisableTiming);
        cudaEventCreateWithFlags(&ev2, cudaEventDisableTiming);
        cudaEventCreateWithFlags(&ev3, cudaEventDisableTiming);
    }

    cudaFuncSetAttribute(attn_mma, cudaFuncAttributeMaxDynamicSharedMemorySize, AT_SMEM);
    cudaFuncSetAttribute(gemm_mma<bf16,false,false,false,false>, cudaFuncAttributeMaxDynamicSharedMemorySize, GEMM_SMEM);
    cudaFuncSetAttribute(gemm_mma<float,false,true,false,false>, cudaFuncAttributeMaxDynamicSharedMemorySize, GEMM_SMEM);
    cudaFuncSetAttribute(gemm_mma<bf16,true,false,true,false>,   cudaFuncAttributeMaxDynamicSharedMemorySize, GEMM_SMEM);
    cudaFuncSetAttribute(gemm_mma<float,false,false,false,true>, cudaFuncAttributeMaxDynamicSharedMemorySize, GEMM_SMEM);

    // Fork: ALL weight prep on side stream. ipw16 first (QKV gates on evA).
    cudaEventRecord(ev0, 0);
    cudaStreamWaitEvent(s2, ev0, 0);
    bf16_copy<<<(3*Dm*Dm/4 + 255)/256, 256, 0, s2>>>(ipw, ipw16, 3*Dm*Dm/4);
    cudaEventRecord(evA, s2);
    bf16_copy<<<(Dm*Dm/4 + 255)/256, 256, 0, s2>>>(opw, opw16, Dm*Dm/4);
    transpose_bf16<<<dim3(Ff/32, Dm/32, Ee), dim3(32,8), 0, s2>>>(w1, w1t, Dm, Ff);
    transpose_bf16<<<dim3(Dm/32, Ff/32, Ee), dim3(32,8), 0, s2>>>(w2, w2t, Ff, Dm);
    cudaEventRecord(ev1, s2);

    // Main stream: LN1 overlaps ipw copy.
    ln_kernel<<<Ntok, 256>>>(src, ln1g, ln1b, xln);
    cudaStreamWaitEvent(0, evA, 0);
    // 2. QKV -> bf16
    gemm_mma<bf16,false,false,false,false><<<dim3(3072/BN, Ntok/BM), 256, GEMM_SMEM>>>(
        xln, ipw16, ipb, nullptr, qkv, 3072, 1024, 1<<30, 0, 0, nullptr, nullptr);
    // 3. Attention -> bf16
    attn_mma<<<dim3(Sq/128, Bc*Hh), 256, AT_SMEM>>>(qkv, pad, attn);
    cudaStreamWaitEvent(0, ev1, 0);
    // 4. out_proj + residual(src) -> out directly
    gemm_mma<float,false,true,false,false><<<dim3(1024/BN, Ntok/BM), 256, GEMM_SMEM>>>(
        attn, opw16, opb, src, out, 1024, 1024, 1<<30, 0, 0, nullptr, nullptr);
    // 5. LN2 + router fused (reads src1 values from out)
    ln2_router<<<Ntok, 256>>>(out, ln2g, ln2b, x2b, rw, rb, pad);
    // 6. Scan
    scan_kernel<<<1, 1024>>>(pad);
    // Fork: loss on side stream.
    cudaEventRecord(ev2, 0);
    cudaStreamWaitEvent(s2, ev2, 0);
    loss_kernel<<<1, 256, 0, s2>>>(pad, out);
    cudaEventRecord(ev3, s2);
    // 7. FFN1 (gather, relu, empty-tile skip)
    gemm_mma<bf16,true,false,true,false><<<dim3(Ff/BN, SLOTS/BM), 256, GEMM_SMEM>>>(
        x2b, w1t, b1, nullptr, hb, Ff, 1024, CAP, (long long)Dm*Ff, Ff, tok, nullptr);
    // 8. FFN2 (scatter-add into out with gate, empty-tile skip)
    gemm_mma<float,false,false,false,true><<<dim3(Dm/BN, SLOTS/BM), 256, GEMM_SMEM>>>(
        hb, w2t, b2, nullptr, out, 1024, Ff, CAP, (long long)Ff*Dm, Dm, tok, gate);
    cudaStreamWaitEvent(0, ev3, 0);
}

// round 14
// speedup vs baseline: 1.0332x; 1.0332x over previous
#include <cuda_runtime.h>
#include <cuda_bf16.h>
#include <math.h>
#include <stdint.h>

// ---------------------------------------------------------------------------
// Problem constants
// ---------------------------------------------------------------------------
#define Bc   4
#define Sq   2048
#define Dm   1024
#define Hh   16
#define Ee   8
#define Ff   4096
#define Ntok (Bc*Sq)          // 8192
#define CAP  1280
#define SLOTS (Ee*CAP)        // 10240

typedef __nv_bfloat16 bf16;
typedef __nv_bfloat162 bf162;

// ---------------------------------------------------------------------------
// Device scratch
// ---------------------------------------------------------------------------
__device__ bf16  g_xln [Ntok*Dm];
__device__ bf16  g_qkv [Ntok*3*Dm];
__device__ bf16  g_attn[Ntok*Dm];
__device__ bf16  g_x2b [Ntok*Dm];
__device__ bf16  g_hbuf[(size_t)SLOTS*Ff];
__device__ float g_probs[Ntok*Ee];
__device__ float g_zterm[Ntok];
__device__ float g_gate [Ntok];
__device__ int   g_eidx [Ntok];
__device__ int   g_tok  [SLOTS];
__device__ int   g_cnt  [Ee];
// bf16 weight copies / transposes ([N,K] layouts)
__device__ bf16 g_ipw16[3*Dm*Dm];
__device__ bf16 g_opw16[Dm*Dm];
__device__ bf16 g_w1t [(size_t)Ee*Ff*Dm];   // [E][F][D]
__device__ bf16 g_w2t [(size_t)Ee*Dm*Ff];   // [E][D][F]

// ---------------------------------------------------------------------------
// Helpers
// ---------------------------------------------------------------------------
__device__ __forceinline__ uint32_t smem_u32(const void* p) {
    uint32_t a;
    asm("{ .reg .u64 t; cvta.to.shared.u64 t, %1; cvt.u32.u64 %0, t; }"
        : "=r"(a) : "l"(p));
    return a;
}
__device__ __forceinline__ void cp16(uint32_t dst, const void* src) {
    asm volatile("cp.async.cg.shared.global [%0], [%1], 16;" :: "r"(dst), "l"(src));
}
__device__ __forceinline__ void cp16z(uint32_t dst, const void* src, uint32_t sz) {
    asm volatile("cp.async.cg.shared.global [%0], [%1], 16, %2;"
                 :: "r"(dst), "l"(src), "r"(sz));
}
__device__ __forceinline__ void ldm_x4(uint32_t* r, uint32_t addr) {
    asm volatile("ldmatrix.sync.aligned.m8n8.x4.shared.b16 {%0,%1,%2,%3}, [%4];"
        : "=r"(r[0]), "=r"(r[1]), "=r"(r[2]), "=r"(r[3]) : "r"(addr));
}
__device__ __forceinline__ void ldm_x4t(uint32_t* r, uint32_t addr) {
    asm volatile("ldmatrix.sync.aligned.m8n8.x4.trans.shared.b16 {%0,%1,%2,%3}, [%4];"
        : "=r"(r[0]), "=r"(r[1]), "=r"(r[2]), "=r"(r[3]) : "r"(addr));
}
__device__ __forceinline__ void mma_bf16(float* d, const uint32_t* a,
                                         uint32_t b0, uint32_t b1) {
    asm volatile(
        "mma.sync.aligned.m16n8k16.row.col.f32.bf16.bf16.f32 "
        "{%0,%1,%2,%3}, {%4,%5,%6,%7}, {%8,%9}, {%0,%1,%2,%3};"
        : "+f"(d[0]), "+f"(d[1]), "+f"(d[2]), "+f"(d[3])
        : "r"(a[0]), "r"(a[1]), "r"(a[2]), "r"(a[3]), "r"(b0), "r"(b1));
}
__device__ __forceinline__ uint32_t pack_bf(float lo, float hi) {
    bf162 v = __float22bfloat162_rn(make_float2(lo, hi));
    return *(uint32_t*)&v;
}
// fast exp via exp2 polynomial on the FMA pipe (MUFU is slow on B300)
__device__ __forceinline__ float expp(float x) {
    float y = fmaxf(x * 1.4426950408889634f, -120.f);
    float t = y + 12582912.f;
    int   e = __float_as_int(t);
    float r = t - 12582912.f;
    float f = y - r;
    float p = 1.3333558146e-3f;
    p = fmaf(p, f, 9.6181291076e-3f);
    p = fmaf(p, f, 5.5504108664e-2f);
    p = fmaf(p, f, 2.4022650696e-1f);
    p = fmaf(p, f, 6.9314718056e-1f);
    p = fmaf(p, f, 1.0f);
    float sc = __int_as_float((e - 0x4b400000 + 127) << 23);
    return p * sc;
}

__device__ __forceinline__ void store_pair(float* C, size_t off, float v0, float v1) {
    *(float2*)(C + off) = make_float2(v0, v1);
}
__device__ __forceinline__ void store_pair(bf16* C, size_t off, float v0, float v1) {
    *(bf162*)(C + off) = __float22bfloat162_rn(make_float2(v0, v1));
}

// ---------------------------------------------------------------------------
// bf16 mma GEMM: C[M,N] = A[M,K] @ B[N,K]^T (+bias, relu, residual)
// 128x256 block tile, 128-half k-chunk (272B padded rows), 2-stage double
// buffer, 8 warps (2m x 4n), warp tile 64x64. ONE __syncthreads per k-chunk.
// (exact R12 configuration — interleaved B-fragment loads)
// ---------------------------------------------------------------------------
#define BM 128
#define BN 256
#define KCH 128
#define RSTR 272                     // 256B data + 16B pad
#define STAGE_B ((BM+BN)*RSTR)       // 104448 bytes
#define GEMM_SMEM (2*STAGE_B + 512)  // 209408

template<typename TO, bool RELU, bool RES, bool GATHER, bool SCATTER>
__global__ __launch_bounds__(256, 1) void gemm_mma(
    const bf16* __restrict__ A, const bf16* __restrict__ Bm,
    const float* __restrict__ bias, const float* __restrict__ Res,
    TO* __restrict__ C, int Nld, int K,
    int rowsPerExpert, long long bExpStride, int biasExpStride,
    const int* __restrict__ tokIdx, const float* __restrict__ gate)
{
    extern __shared__ char smem[];
    const uint32_t sb0 = smem_u32(smem);
    int* stok = (int*)(smem + 2*STAGE_B);
    const int tid = threadIdx.x;
    const int wid = tid >> 5, lane = tid & 31;
    const int j8 = lane & 7, gi = lane >> 3;
    const int lr = lane >> 2, lc = lane & 3;
    const int row0 = blockIdx.y * BM, col0 = blockIdx.x * BN;
    const int expert = row0 / rowsPerExpert;
    const bf16* Bexp = Bm + (long long)expert * bExpStride;
    const float* bb  = bias + (long long)expert * biasExpStride;
    const int m0 = (wid & 1) * 64, n0 = (wid >> 1) * 64;

    const bf16* Abase = GATHER ? A : A + (size_t)row0 * K;
    const bf16* Bbase = Bexp + (size_t)col0 * K;

    if (GATHER || SCATTER) {
        int v = 0;
        if (tid < BM) {
            int t = tokIdx[row0 + tid];
            stok[tid] = t;
            v = (t >= 0);
        }
        if (!__syncthreads_or(v)) return;   // whole tile empty -> no effect
    }

    const int arow = j8 + (gi & 1) * 8;
    const int aoff = (gi >> 1) * 16;
    const int brow = j8 + (gi >> 1) * 8;
    const int boff = (gi & 1) * 16;

    float acc[4][8][4];
#pragma unroll
    for (int mt = 0; mt < 4; mt++)
#pragma unroll
        for (int t = 0; t < 8; t++)
#pragma unroll
            for (int q = 0; q < 4; q++) acc[mt][t][q] = 0.f;

    const int nch = K / KCH;

    auto load_stage = [&](int s, int ch) {
        const uint32_t sa  = sb0 + (uint32_t)s * STAGE_B;
        const uint32_t sbm = sa + BM * RSTR;
        const bf16* Bcp = Bbase + ch * KCH;
#pragma unroll
        for (int q = 0; q < 8; q++) {          // A: 2048 segs of 16B
            int seg = tid + 256 * q;
            int r = seg >> 4, c = seg & 15;
            if (GATHER) {
                int t = stok[r];
                uint32_t sz = (t >= 0) ? 16u : 0u;
                const bf16* srcp = Abase + (size_t)(t >= 0 ? t : 0) * K + ch * KCH + c * 8;
                cp16z(sa + (uint32_t)(r * RSTR + c * 16), srcp, sz);
            } else {
                cp16(sa + (uint32_t)(r * RSTR + c * 16),
                     Abase + (size_t)r * K + ch * KCH + c * 8);
            }
        }
#pragma unroll
        for (int q = 0; q < 16; q++) {         // B: 4096 segs of 16B
            int seg = tid + 256 * q;
            int r = seg >> 4, c = seg & 15;
            cp16(sbm + (uint32_t)(r * RSTR + c * 16), Bcp + (size_t)r * K + c * 8);
        }
    };

    load_stage(0, 0);
    asm volatile("cp.async.commit_group;");

    for (int i = 0; i < nch; i++) {
        asm volatile("cp.async.wait_group 0;");
        __syncthreads();
        if (i + 1 < nch) load_stage((i + 1) & 1, i + 1);
        asm volatile("cp.async.commit_group;");

        const uint32_t sa  = sb0 + (uint32_t)(i & 1) * STAGE_B;
        const uint32_t sbm = sa + BM * RSTR;
#pragma unroll
        for (int kk = 0; kk < KCH/16; kk++) {
            uint32_t af[4][4];
#pragma unroll
            for (int mt = 0; mt < 4; mt++)
                ldm_x4(af[mt], sa + (uint32_t)((m0 + mt * 16 + arow) * RSTR + kk * 32 + aoff));
#pragma unroll
            for (int nt = 0; nt < 4; nt++) {
                uint32_t bfr[4];
                ldm_x4(bfr, sbm + (uint32_t)((n0 + nt * 16 + brow) * RSTR + kk * 32 + boff));
#pragma unroll
                for (int mt = 0; mt < 4; mt++) {
                    mma_bf16(acc[mt][nt * 2 + 0], af[mt], bfr[0], bfr[1]);
                    mma_bf16(acc[mt][nt * 2 + 1], af[mt], bfr[2], bfr[3]);
                }
            }
        }
    }

    // epilogue
#pragma unroll
    for (int mt = 0; mt < 4; mt++) {
        const int gr = row0 + m0 + mt * 16 + lr;
        int t0 = 0, t1 = 0;
        float g0 = 0.f, g1 = 0.f;
        if (SCATTER) {
            t0 = stok[m0 + mt * 16 + lr]; t1 = stok[m0 + mt * 16 + lr + 8];
            g0 = (t0 >= 0) ? gate[t0] : 0.f;
            g1 = (t1 >= 0) ? gate[t1] : 0.f;
        }
#pragma unroll
        for (int nt = 0; nt < 4; nt++) {
#pragma unroll
            for (int pr = 0; pr < 2; pr++) {
                const int gc = col0 + n0 + nt * 16 + pr * 8 + lc * 2;
                float* d = acc[mt][nt * 2 + pr];
                float b0 = bb[gc], b1 = bb[gc + 1];
                float v0 = d[0] + b0, v1 = d[1] + b1;
                float v2 = d[2] + b0, v3 = d[3] + b1;
                if (RELU) {
                    v0 = fmaxf(v0, 0.f); v1 = fmaxf(v1, 0.f);
                    v2 = fmaxf(v2, 0.f); v3 = fmaxf(v3, 0.f);
                }
                if (RES) {
                    float2 r0 = *(const float2*)(Res + (size_t)gr * Nld + gc);
                    float2 r1 = *(const float2*)(Res + (size_t)(gr + 8) * Nld + gc);
                    v0 += r0.x; v1 += r0.y; v2 += r1.x; v3 += r1.y;
                }
                if (SCATTER) {
                    if (t0 >= 0) {
                        float2 cur = *(float2*)((float*)C + (size_t)t0 * Nld + gc);
                        *(float2*)((float*)C + (size_t)t0 * Nld + gc) =
                            make_float2(cur.x + g0 * v0, cur.y + g0 * v1);
                    }
                    if (t1 >= 0) {
                        float2 cur = *(float2*)((float*)C + (size_t)t1 * Nld + gc);
                        *(float2*)((float*)C + (size_t)t1 * Nld + gc) =
                            make_float2(cur.x + g1 * v2, cur.y + g1 * v3);
                    }
                } else {
                    store_pair(C, (size_t)gr * Nld + gc, v0, v1);
                    store_pair(C, (size_t)(gr + 8) * Nld + gc, v2, v3);
                }
            }
        }
    }
}

// ---------------------------------------------------------------------------
// Flash attention, bf16 mma. 256 threads (8 warps), q-tile 128, k-tiles of 64.
// ONE __syncthreads per k-tile. (R12 config + min 2 CTAs/SM for overlap)
// ---------------------------------------------------------------------------
#define AT_SMEM (18432 + 9216*4 + 512)

__global__ __launch_bounds__(256, 2) void attn_mma(
    const bf16* __restrict__ qkv,
    const unsigned char* __restrict__ pad,
    bf16* __restrict__ outp)
{
    extern __shared__ char smem[];
    const uint32_t sQ  = smem_u32(smem);
    const uint32_t sK0 = sQ + 18432;
    const uint32_t sV0 = sK0 + 9216 * 2;
    float* mkp = (float*)(smem + 18432 + 9216 * 4);

    const int tid = threadIdx.x;
    const int wid = tid >> 5, lane = tid & 31;
    const int j8 = lane & 7, gi = lane >> 3;
    const int lc = lane & 3, lr = lane >> 2;
    const int bh = blockIdx.y, b = bh >> 4, h = bh & 15;
    const int q0 = blockIdx.x * 128;
    const size_t tokBase = (size_t)b * Sq;

    {
        const bf16* qb = qkv + (tokBase + q0) * 3072 + h * 64;
#pragma unroll
        for (int q = 0; q < 4; q++) {
            int seg = tid + 256 * q;
            int r = seg >> 3, c = seg & 7;
            cp16(sQ + (uint32_t)(r * 144 + c * 16), qb + (size_t)r * 3072 + c * 8);
        }
    }
    asm volatile("cp.async.commit_group;");

    auto prefetch = [&](int st, int kt) {
        const int k0 = kt * 64;
        const bf16* kb = qkv + (tokBase + k0) * 3072 + 1024 + h * 64;
        const bf16* vb = qkv + (tokBase + k0) * 3072 + 2048 + h * 64;
        const uint32_t sk = sK0 + (uint32_t)st * 9216, sv = sV0 + (uint32_t)st * 9216;
#pragma unroll
        for (int q = 0; q < 2; q++) {
            int seg = tid + 256 * q;
            int r = seg >> 3, c = seg & 7;
            cp16(sk + (uint32_t)(r * 144 + c * 16), kb + (size_t)r * 3072 + c * 8);
            cp16(sv + (uint32_t)(r * 144 + c * 16), vb + (size_t)r * 3072 + c * 8);
        }
        if (tid < 64) mkp[st * 64 + tid] = pad[tokBase + k0 + tid] ? -1e9f : 0.f;
    };

    prefetch(0, 0);
    asm volatile("cp.async.commit_group;");
    asm volatile("cp.async.wait_group 1;");
    __syncthreads();

    const int arow = j8 + (gi & 1) * 8, aoff = (gi >> 1) * 16;
    const int brow = j8 + (gi >> 1) * 8, boff = (gi & 1) * 16;

    uint32_t qa[4][4];
#pragma unroll
    for (int kd = 0; kd < 4; kd++)
        ldm_x4(qa[kd], sQ + (uint32_t)((wid * 16 + arow) * 144 + kd * 32 + aoff));

    float m0v = -1e30f, m1v = -1e30f, l0 = 0.f, l1 = 0.f;
    float o[8][4];
#pragma unroll
    for (int dt = 0; dt < 8; dt++)
#pragma unroll
        for (int q = 0; q < 4; q++) o[dt][q] = 0.f;

    for (int kt = 0; kt < Sq / 64; kt++) {
        const int st = kt & 1;
        asm volatile("cp.async.wait_group 0;");
        __syncthreads();
        if (kt + 1 < Sq / 64) prefetch(st ^ 1, kt + 1);
        asm volatile("cp.async.commit_group;");

        const uint32_t sk = sK0 + (uint32_t)st * 9216, sv = sV0 + (uint32_t)st * 9216;
        float s[8][4];
#pragma unroll
        for (int j = 0; j < 8; j++)
#pragma unroll
            for (int q = 0; q < 4; q++) s[j][q] = 0.f;

#pragma unroll
        for (int jp = 0; jp < 4; jp++) {
#pragma unroll
            for (int kd = 0; kd < 4; kd++) {
                uint32_t bfr[4];
                ldm_x4(bfr, sk + (uint32_t)((jp * 16 + brow) * 144 + kd * 32 + boff));
                mma_bf16(s[2 * jp],     qa[kd], bfr[0], bfr[1]);
                mma_bf16(s[2 * jp + 1], qa[kd], bfr[2], bfr[3]);
            }
        }

        float rmax0 = -1e30f, rmax1 = -1e30f;
#pragma unroll
        for (int j = 0; j < 8; j++) {
            float mka = mkp[st * 64 + j * 8 + 2 * lc];
            float mkb = mkp[st * 64 + j * 8 + 2 * lc + 1];
            s[j][0] = fmaf(s[j][0], 0.125f, mka);
            s[j][1] = fmaf(s[j][1], 0.125f, mkb);
            s[j][2] = fmaf(s[j][2], 0.125f, mka);
            s[j][3] = fmaf(s[j][3], 0.125f, mkb);
            rmax0 = fmaxf(rmax0, fmaxf(s[j][0], s[j][1]));
            rmax1 = fmaxf(rmax1, fmaxf(s[j][2], s[j][3]));
        }
        rmax0 = fmaxf(rmax0, __shfl_xor_sync(0xffffffffu, rmax0, 1));
        rmax0 = fmaxf(rmax0, __shfl_xor_sync(0xffffffffu, rmax0, 2));
        rmax1 = fmaxf(rmax1, __shfl_xor_sync(0xffffffffu, rmax1, 1));
        rmax1 = fmaxf(rmax1, __shfl_xor_sync(0xffffffffu, rmax1, 2));
        float nm0 = fmaxf(m0v, rmax0), nm1 = fmaxf(m1v, rmax1);
        float c0 = expp(m0v - nm0), c1 = expp(m1v - nm1);
        m0v = nm0; m1v = nm1;
        float rs0 = 0.f, rs1 = 0.f;
#pragma unroll
        for (int j = 0; j < 8; j++) {
            s[j][0] = expp(s[j][0] - nm0); s[j][1] = expp(s[j][1] - nm0);
            s[j][2] = expp(s[j][2] - nm1); s[j][3] = expp(s[j][3] - nm1);
            rs0 += s[j][0] + s[j][1];
            rs1 += s[j][2] + s[j][3];
        }
        rs0 += __shfl_xor_sync(0xffffffffu, rs0, 1);
        rs0 += __shfl_xor_sync(0xffffffffu, rs0, 2);
        rs1 += __shfl_xor_sync(0xffffffffu, rs1, 1);
        rs1 += __shfl_xor_sync(0xffffffffu, rs1, 2);
        l0 = l0 * c0 + rs0; l1 = l1 * c1 + rs1;
#pragma unroll
        for (int dt = 0; dt < 8; dt++) {
            o[dt][0] *= c0; o[dt][1] *= c0; o[dt][2] *= c1; o[dt][3] *= c1;
        }

        uint32_t pa[4][4];
#pragma unroll
        for (int t = 0; t < 4; t++) {
            pa[t][0] = pack_bf(s[2 * t][0],     s[2 * t][1]);
            pa[t][1] = pack_bf(s[2 * t][2],     s[2 * t][3]);
            pa[t][2] = pack_bf(s[2 * t + 1][0], s[2 * t + 1][1]);
            pa[t][3] = pack_bf(s[2 * t + 1][2], s[2 * t + 1][3]);
        }
#pragma unroll
        for (int t = 0; t < 4; t++) {
#pragma unroll
            for (int dp = 0; dp < 4; dp++) {
                uint32_t vf[4];
                ldm_x4t(vf, sv + (uint32_t)((t * 16 + arow) * 144 + dp * 32 + aoff));
                mma_bf16(o[2 * dp],     pa[t], vf[0], vf[1]);
                mma_bf16(o[2 * dp + 1], pa[t], vf[2], vf[3]);
            }
        }
    }

    float inv0 = 1.f / l0, inv1 = 1.f / l1;
    const int rg = q0 + wid * 16 + lr;
    bf16* ob = outp + (tokBase + rg) * Dm + h * 64;
#pragma unroll
    for (int dt = 0; dt < 8; dt++) {
        *(bf162*)(ob + dt * 8 + 2 * lc) =
            __float22bfloat162_rn(make_float2(o[dt][0] * inv0, o[dt][1] * inv0));
        *(bf162*)(ob + (size_t)8 * Dm + dt * 8 + 2 * lc) =
            __float22bfloat162_rn(make_float2(o[dt][2] * inv1, o[dt][3] * inv1));
    }
}

// ---------------------------------------------------------------------------
// LayerNorm (bf16 out, for LN1)
// ---------------------------------------------------------------------------
__global__ __launch_bounds__(256) void ln_kernel(const float* __restrict__ in,
                                                 const float* __restrict__ g,
                                                 const float* __restrict__ b,
                                                 bf16* __restrict__ out)
{
    int n = blockIdx.x, tid = threadIdx.x;
    float4 v = ((const float4*)(in + (size_t)n*Dm))[tid];
    float s  = v.x+v.y+v.z+v.w;
    float s2 = v.x*v.x+v.y*v.y+v.z*v.z+v.w*v.w;
    __shared__ float r1[256], r2[256];
    r1[tid]=s; r2[tid]=s2; __syncthreads();
    for (int st=128; st; st>>=1) {
        if (tid<st) { r1[tid]+=r1[tid+st]; r2[tid]+=r2[tid+st]; }
        __syncthreads();
    }
    float mean = r1[0]*(1.0f/Dm);
    float var  = r2[0]*(1.0f/Dm) - mean*mean;
    float rstd = rsqrtf(var + 1e-5f);
    float4 gg = ((const float4*)g)[tid];
    float4 bb = ((const float4*)b)[tid];
    float o0 = (v.x-mean)*rstd*gg.x + bb.x;
    float o1 = (v.y-mean)*rstd*gg.y + bb.y;
    float o2 = (v.z-mean)*rstd*gg.z + bb.z;
    float o3 = (v.w-mean)*rstd*gg.w + bb.w;
    size_t base = (size_t)n*Dm + tid*4;
    store_pair(out, base, o0, o1);
    store_pair(out, base + 2, o2, o3);
}

// ---------------------------------------------------------------------------
// LN2 + router fused (reads src1 values from `out` buffer)
// ---------------------------------------------------------------------------
__global__ __launch_bounds__(256) void ln2_router(const float* __restrict__ in,
                                                  const float* __restrict__ g,
                                                  const float* __restrict__ b,
                                                  bf16* __restrict__ outh,
                                                  const float* __restrict__ rw,
                                                  const float* __restrict__ rb,
                                                  const unsigned char* __restrict__ pad)
{
    int n = blockIdx.x, tid = threadIdx.x;
    __shared__ float r1[256], r2[256];
    __shared__ float xs[1024];
    __shared__ float lg[8];
    float4 v = ((const float4*)(in + (size_t)n*Dm))[tid];
    float s  = v.x+v.y+v.z+v.w;
    float s2 = v.x*v.x+v.y*v.y+v.z*v.z+v.w*v.w;
    r1[tid]=s; r2[tid]=s2; __syncthreads();
    for (int st=128; st; st>>=1) {
        if (tid<st) { r1[tid]+=r1[tid+st]; r2[tid]+=r2[tid+st]; }
        __syncthreads();
    }
    float mean = r1[0]*(1.0f/Dm);
    float var  = r2[0]*(1.0f/Dm) - mean*mean;
    float rstd = rsqrtf(var + 1e-5f);
    float4 gg = ((const float4*)g)[tid];
    float4 bb = ((const float4*)b)[tid];
    float4 o;
    o.x = (v.x-mean)*rstd*gg.x + bb.x;
    o.y = (v.y-mean)*rstd*gg.y + bb.y;
    o.z = (v.z-mean)*rstd*gg.z + bb.z;
    o.w = (v.w-mean)*rstd*gg.w + bb.w;
    bf162* hp = (bf162*)(outh + (size_t)n*Dm);
    hp[tid*2]   = __float22bfloat162_rn(make_float2(o.x, o.y));
    hp[tid*2+1] = __float22bfloat162_rn(make_float2(o.z, o.w));
    ((float4*)xs)[tid] = o;
    __syncthreads();
    int w = tid >> 5, lane = tid & 31;
    float acc = 0.f;
    for (int i = lane; i < 1024; i += 32) acc += xs[i] * rw[i*8 + w];
    for (int off=16; off; off>>=1) acc += __shfl_xor_sync(0xffffffffu, acc, off);
    if (lane == 0) lg[w] = acc + rb[w];
    __syncthreads();
    if (tid == 0) {
        float mx = lg[0]; int ei = 0;
        for (int e=1;e<8;e++) if (lg[e] > mx) { mx = lg[e]; ei = e; }
        float pr[8], se = 0.f;
        for (int e=0;e<8;e++) { pr[e] = expf(lg[e]-mx); se += pr[e]; }
        float inv = 1.f/se;
        bool valid = (pad[n] == 0);
        float tm = valid ? 1.f : 0.f;
        for (int e=0;e<8;e++) g_probs[n*8+e] = pr[e]*inv*tm;
        g_gate[n] = pr[ei]*inv;
        g_eidx[n] = ei;
        float lse = mx + logf(se);
        g_zterm[n] = lse*lse*tm;
    }
}

// ---------------------------------------------------------------------------
// Weight prep
// ---------------------------------------------------------------------------
__global__ __launch_bounds__(256) void bf16_copy(const float* __restrict__ in,
                                                 bf16* __restrict__ out, int n4)
{
    int i = blockIdx.x*256 + threadIdx.x;
    if (i < n4) {
        float4 v = ((const float4*)in)[i];
        ((bf162*)out)[i*2]   = __float22bfloat162_rn(make_float2(v.x, v.y));
        ((bf162*)out)[i*2+1] = __float22bfloat162_rn(make_float2(v.z, v.w));
    }
}

__global__ __launch_bounds__(256) void transpose_bf16(const float* __restrict__ in,
                                                      bf16* __restrict__ out,
                                                      int R, int Cc)
{
    __shared__ float t[32][33];
    int e = blockIdx.z;
    const float* ip = in  + (size_t)e*R*Cc;
    bf16* op        = out + (size_t)e*R*Cc;
    int c0 = blockIdx.x*32, r0 = blockIdx.y*32;
    int tx = threadIdx.x, ty = threadIdx.y;
#pragma unroll
    for (int j=0;j<32;j+=8)
        t[ty+j][tx] = ip[(size_t)(r0+ty+j)*Cc + c0+tx];
    __syncthreads();
#pragma unroll
    for (int j=0;j<32;j+=8)
        op[(size_t)(c0+ty+j)*R + r0+tx] = __float2bfloat16_rn(t[tx][ty+j]);
}

// ---------------------------------------------------------------------------
// Routing scan
// ---------------------------------------------------------------------------
__global__ __launch_bounds__(1024) void scan_kernel(const unsigned char* __restrict__ pad)
{
    __shared__ unsigned char sc[Ntok];
    __shared__ int base[8];
    int tid = threadIdx.x;
    for (int i = tid; i < SLOTS; i += 1024) g_tok[i] = -1;
    for (int i = tid; i < Ntok; i += 1024)
        sc[i] = (unsigned char)(g_eidx[i] | (pad[i] ? 0 : 16));
    if (tid < 8) base[tid] = 0;
    __syncthreads();
    if (tid < 32) {
        int lane = tid;
        for (int c = 0; c < Ntok/32; c++) {
            int i = c*32 + lane;
            int code = sc[i];
            int e = code & 7;
            bool valid = (code & 16) != 0;
            unsigned peers = __match_any_sync(0xffffffffu, e);
            unsigned vmask = __ballot_sync(0xffffffffu, valid);
            unsigned pv = peers & vmask;
            int myrank = __popc(pv & ((1u << lane) - 1u));
            int b0 = base[e];
            __syncwarp();
            int pos = b0 + myrank;
            bool keep = valid && (pos < CAP);
            if (keep) g_tok[e*CAP + pos] = i;
            if (valid && lane == (__ffs(pv) - 1)) base[e] = b0 + __popc(pv);
            __syncwarp();
        }
        if (lane < 8) g_cnt[lane] = base[lane];
    }
}

// ---------------------------------------------------------------------------
// Loss reduction
// ---------------------------------------------------------------------------
__global__ __launch_bounds__(256) void loss_kernel(const unsigned char* __restrict__ pad,
                                                   float* __restrict__ out)
{
    int tid = threadIdx.x;
    float zs = 0.f, ps[8];
    int cnt = 0;
#pragma unroll
    for (int e=0;e<8;e++) ps[e]=0.f;
    for (int n = tid; n < Ntok; n += 256) {
        if (pad[n] == 0) cnt++;
        zs += g_zterm[n];
#pragma unroll
        for (int e=0;e<8;e++) ps[e] += g_probs[n*8+e];
    }
    __shared__ float red[256];
    __shared__ float res[10];
    float vals[10];
    vals[0] = (float)cnt; vals[1] = zs;
    for (int e=0;e<8;e++) vals[2+e] = ps[e];
    for (int q=0;q<10;q++) {
        red[tid] = vals[q]; __syncthreads();
        for (int st=128; st; st>>=1) {
            if (tid < st) red[tid] += red[tid+st];
            __syncthreads();
        }
        if (tid == 0) res[q] = red[0];
        __syncthreads();
    }
    if (tid == 0) {
        float denom = fmaxf(res[0], 1.f);
        float lb = 0.f;
        for (int e=0;e<8;e++) lb += ((float)g_cnt[e]/denom) * (res[2+e]/denom);
        lb *= (float)Ee;
        out[(size_t)Ntok*Dm]     = lb;
        out[(size_t)Ntok*Dm + 1] = res[1]/denom;
    }
}

// ---------------------------------------------------------------------------
// Launch
// ---------------------------------------------------------------------------
extern "C" void kernel_launch(void* const* d_in, const int* in_sizes, int n_in,
                              void* d_out, int out_size)
{
    const float* src  = (const float*)d_in[0];
    const unsigned char* pad = (const unsigned char*)d_in[1];
    const float* ln1g = (const float*)d_in[2];
    const float* ln1b = (const float*)d_in[3];
    const float* ipw  = (const float*)d_in[4];
    const float* ipb  = (const float*)d_in[5];
    const float* opw  = (const float*)d_in[6];
    const float* opb  = (const float*)d_in[7];
    const float* ln2g = (const float*)d_in[8];
    const float* ln2b = (const float*)d_in[9];
    const float* rw   = (const float*)d_in[10];
    const float* rb   = (const float*)d_in[11];
    const float* w1   = (const float*)d_in[12];
    const float* b1   = (const float*)d_in[13];
    const float* w2   = (const float*)d_in[14];
    const float* b2   = (const float*)d_in[15];
    float* out = (float*)d_out;

    bf16 *xln, *qkv, *attn, *x2b, *hb, *ipw16, *opw16, *w1t, *w2t;
    float *gate;
    int *tok;
    cudaGetSymbolAddress((void**)&xln,  g_xln);
    cudaGetSymbolAddress((void**)&qkv,  g_qkv);
    cudaGetSymbolAddress((void**)&attn, g_attn);
    cudaGetSymbolAddress((void**)&x2b,  g_x2b);
    cudaGetSymbolAddress((void**)&hb,   g_hbuf);
    cudaGetSymbolAddress((void**)&ipw16, g_ipw16);
    cudaGetSymbolAddress((void**)&opw16, g_opw16);
    cudaGetSymbolAddress((void**)&w1t,  g_w1t);
    cudaGetSymbolAddress((void**)&w2t,  g_w2t);
    cudaGetSymbolAddress((void**)&tok,  g_tok);
    cudaGetSymbolAddress((void**)&gate, g_gate);

    static cudaStream_t s2 = nullptr;
    static cudaEvent_t ev0 = nullptr, evA = nullptr, ev1 = nullptr,
                       ev2 = nullptr, ev3 = nullptr;
    if (!s2) {
        cudaStreamCreateWithFlags(&s2, cudaStreamNonBlocking);
        cudaEventCreateWithFlags(&ev0, cudaEventDisableTiming);
        cudaEventCreateWithFlags(&evA, cudaEventDisableTiming);
        cudaEventCreateWithFlags(&ev1, cudaEventDisableTiming);
        cudaEventCreateWithFlags(&ev2, cudaEventDisableTiming);
        cudaEventCreateWithFlags(&ev3, cudaEventDisableTiming);
    }

    cudaFuncSetAttribute(attn_mma, cudaFuncAttributeMaxDynamicSharedMemorySize, AT_SMEM);
    cudaFuncSetAttribute(gemm_mma<bf16,false,false,false,false>, cudaFuncAttributeMaxDynamicSharedMemorySize, GEMM_SMEM);
    cudaFuncSetAttribute(gemm_mma<float,false,true,false,false>, cudaFuncAttributeMaxDynamicSharedMemorySize, GEMM_SMEM);
    cudaFuncSetAttribute(gemm_mma<bf16,true,false,true,false>,   cudaFuncAttributeMaxDynamicSharedMemorySize, GEMM_SMEM);
    cudaFuncSetAttribute(gemm_mma<float,false,false,false,true>, cudaFuncAttributeMaxDynamicSharedMemorySize, GEMM_SMEM);

    // Fork: ALL weight prep on side stream. ipw16 first (QKV gates on evA).
    cudaEventRecord(ev0, 0);
    cudaStreamWaitEvent(s2, ev0, 0);
    bf16_copy<<<(3*Dm*Dm/4 + 255)/256, 256, 0, s2>>>(ipw, ipw16, 3*Dm*Dm/4);
    cudaEventRecord(evA, s2);
    bf16_copy<<<(Dm*Dm/4 + 255)/256, 256, 0, s2>>>(opw, opw16, Dm*Dm/4);
    transpose_bf16<<<dim3(Ff/32, Dm/32, Ee), dim3(32,8), 0, s2>>>(w1, w1t, Dm, Ff);
    transpose_bf16<<<dim3(Dm/32, Ff/32, Ee), dim3(32,8), 0, s2>>>(w2, w2t, Ff, Dm);
    cudaEventRecord(ev1, s2);

    // Main stream: LN1 overlaps ipw copy.
    ln_kernel<<<Ntok, 256>>>(src, ln1g, ln1b, xln);
    cudaStreamWaitEvent(0, evA, 0);
    // 2. QKV -> bf16
    gemm_mma<bf16,false,false,false,false><<<dim3(3072/BN, Ntok/BM), 256, GEMM_SMEM>>>(
        xln, ipw16, ipb, nullptr, qkv, 3072, 1024, 1<<30, 0, 0, nullptr, nullptr);
    // 3. Attention -> bf16
    attn_mma<<<dim3(Sq/128, Bc*Hh), 256, AT_SMEM>>>(qkv, pad, attn);
    cudaStreamWaitEvent(0, ev1, 0);
    // 4. out_proj + residual(src) -> out directly
    gemm_mma<float,false,true,false,false><<<dim3(1024/BN, Ntok/BM), 256, GEMM_SMEM>>>(
        attn, opw16, opb, src, out, 1024, 1024, 1<<30, 0, 0, nullptr, nullptr);
    // 5. LN2 + router fused (reads src1 values from out)
    ln2_router<<<Ntok, 256>>>(out, ln2g, ln2b, x2b, rw, rb, pad);
    // 6. Scan
    scan_kernel<<<1, 1024>>>(pad);
    // Fork: loss on side stream.
    cudaEventRecord(ev2, 0);
    cudaStreamWaitEvent(s2, ev2, 0);
    loss_kernel<<<1, 256, 0, s2>>>(pad, out);
    cudaEventRecord(ev3, s2);
    // 7. FFN1 (gather, relu, empty-tile skip)
    gemm_mma<bf16,true,false,true,false><<<dim3(Ff/BN, SLOTS/BM), 256, GEMM_SMEM>>>(
        x2b, w1t, b1, nullptr, hb, Ff, 1024, CAP, (long long)Dm*Ff, Ff, tok, nullptr);
    // 8. FFN2 (scatter-add into out with gate, empty-tile skip)
    gemm_mma<float,false,false,false,true><<<dim3(Dm/BN, SLOTS/BM), 256, GEMM_SMEM>>>(
        hb, w2t, b2, nullptr, out, 1024, Ff, CAP, (long long)Ff*Dm, Dm, tok, gate);
    cudaStreamWaitEvent(0, ev3, 0);
}

// round 15
// speedup vs baseline: 1.0385x; 1.0051x over previous
#include <cuda_runtime.h>
#include <cuda_bf16.h>
#include <math.h>
#include <stdint.h>

// ---------------------------------------------------------------------------
// Problem constants
// ---------------------------------------------------------------------------
#define Bc   4
#define Sq   2048
#define Dm   1024
#define Hh   16
#define Ee   8
#define Ff   4096
#define Ntok (Bc*Sq)          // 8192
#define CAP  1280
#define SLOTS (Ee*CAP)        // 10240

typedef __nv_bfloat16 bf16;
typedef __nv_bfloat162 bf162;

// ---------------------------------------------------------------------------
// Device scratch
// ---------------------------------------------------------------------------
__device__ bf16  g_xln [Ntok*Dm];
__device__ bf16  g_qkv [Ntok*3*Dm];
__device__ bf16  g_attn[Ntok*Dm];
__device__ bf16  g_x2b [Ntok*Dm];
__device__ bf16  g_hbuf[(size_t)SLOTS*Ff];
__device__ float g_probs[Ntok*Ee];
__device__ float g_zterm[Ntok];
__device__ float g_gate [Ntok];
__device__ int   g_eidx [Ntok];
__device__ int   g_tok  [SLOTS];
__device__ int   g_cnt  [Ee];
// bf16 weight copies / transposes ([N,K] layouts)
__device__ bf16 g_ipw16[3*Dm*Dm];
__device__ bf16 g_opw16[Dm*Dm];
__device__ bf16 g_w1t [(size_t)Ee*Ff*Dm];   // [E][F][D]
__device__ bf16 g_w2t [(size_t)Ee*Dm*Ff];   // [E][D][F]

// ---------------------------------------------------------------------------
// Helpers
// ---------------------------------------------------------------------------
__device__ __forceinline__ uint32_t smem_u32(const void* p) {
    uint32_t a;
    asm("{ .reg .u64 t; cvta.to.shared.u64 t, %1; cvt.u32.u64 %0, t; }"
        : "=r"(a) : "l"(p));
    return a;
}
__device__ __forceinline__ void cp16(uint32_t dst, const void* src) {
    asm volatile("cp.async.cg.shared.global [%0], [%1], 16;" :: "r"(dst), "l"(src));
}
__device__ __forceinline__ void cp16z(uint32_t dst, const void* src, uint32_t sz) {
    asm volatile("cp.async.cg.shared.global [%0], [%1], 16, %2;"
                 :: "r"(dst), "l"(src), "r"(sz));
}
__device__ __forceinline__ void ldm_x4(uint32_t* r, uint32_t addr) {
    asm volatile("ldmatrix.sync.aligned.m8n8.x4.shared.b16 {%0,%1,%2,%3}, [%4];"
        : "=r"(r[0]), "=r"(r[1]), "=r"(r[2]), "=r"(r[3]) : "r"(addr));
}
__device__ __forceinline__ void ldm_x4t(uint32_t* r, uint32_t addr) {
    asm volatile("ldmatrix.sync.aligned.m8n8.x4.trans.shared.b16 {%0,%1,%2,%3}, [%4];"
        : "=r"(r[0]), "=r"(r[1]), "=r"(r[2]), "=r"(r[3]) : "r"(addr));
}
__device__ __forceinline__ void mma_bf16(float* d, const uint32_t* a,
                                         uint32_t b0, uint32_t b1) {
    asm volatile(
        "mma.sync.aligned.m16n8k16.row.col.f32.bf16.bf16.f32 "
        "{%0,%1,%2,%3}, {%4,%5,%6,%7}, {%8,%9}, {%0,%1,%2,%3};"
        : "+f"(d[0]), "+f"(d[1]), "+f"(d[2]), "+f"(d[3])
        : "r"(a[0]), "r"(a[1]), "r"(a[2]), "r"(a[3]), "r"(b0), "r"(b1));
}
__device__ __forceinline__ uint32_t pack_bf(float lo, float hi) {
    bf162 v = __float22bfloat162_rn(make_float2(lo, hi));
    return *(uint32_t*)&v;
}
// fast exp via exp2 polynomial on the FMA pipe (MUFU is slow on B300)
__device__ __forceinline__ float expp(float x) {
    float y = fmaxf(x * 1.4426950408889634f, -120.f);
    float t = y + 12582912.f;
    int   e = __float_as_int(t);
    float r = t - 12582912.f;
    float f = y - r;
    float p = 1.3333558146e-3f;
    p = fmaf(p, f, 9.6181291076e-3f);
    p = fmaf(p, f, 5.5504108664e-2f);
    p = fmaf(p, f, 2.4022650696e-1f);
    p = fmaf(p, f, 6.9314718056e-1f);
    p = fmaf(p, f, 1.0f);
    float sc = __int_as_float((e - 0x4b400000 + 127) << 23);
    return p * sc;
}
// packed variant: identical per-lane IEEE-rn fp32 math, Horner chain runs
// on fma.rn.f32x2 (FFMA2) -> half the FMA-pipe instructions per pair.
__device__ __forceinline__ void expp2(float& xa, float& xb) {
    float ya = fmaxf(xa * 1.4426950408889634f, -120.f);
    float yb = fmaxf(xb * 1.4426950408889634f, -120.f);
    float ta = ya + 12582912.f;
    float tb = yb + 12582912.f;
    int ea = __float_as_int(ta);
    int eb = __float_as_int(tb);
    float fa = ya - (ta - 12582912.f);
    float fb = yb - (tb - 12582912.f);
    uint64_t f2, p2, c;
    asm("mov.b64 %0, {%1,%2};" : "=l"(f2) : "f"(fa), "f"(fb));
    asm("mov.b64 %0, {%1,%1};" : "=l"(p2) : "f"(1.3333558146e-3f));
    asm("mov.b64 %0, {%1,%1};" : "=l"(c)  : "f"(9.6181291076e-3f));
    asm("fma.rn.f32x2 %0, %0, %1, %2;" : "+l"(p2) : "l"(f2), "l"(c));
    asm("mov.b64 %0, {%1,%1};" : "=l"(c)  : "f"(5.5504108664e-2f));
    asm("fma.rn.f32x2 %0, %0, %1, %2;" : "+l"(p2) : "l"(f2), "l"(c));
    asm("mov.b64 %0, {%1,%1};" : "=l"(c)  : "f"(2.4022650696e-1f));
    asm("fma.rn.f32x2 %0, %0, %1, %2;" : "+l"(p2) : "l"(f2), "l"(c));
    asm("mov.b64 %0, {%1,%1};" : "=l"(c)  : "f"(6.9314718056e-1f));
    asm("fma.rn.f32x2 %0, %0, %1, %2;" : "+l"(p2) : "l"(f2), "l"(c));
    asm("mov.b64 %0, {%1,%1};" : "=l"(c)  : "f"(1.0f));
    asm("fma.rn.f32x2 %0, %0, %1, %2;" : "+l"(p2) : "l"(f2), "l"(c));
    float pa, pb;
    asm("mov.b64 {%0,%1}, %2;" : "=f"(pa), "=f"(pb) : "l"(p2));
    xa = pa * __int_as_float((ea - 0x4b400000 + 127) << 23);
    xb = pb * __int_as_float((eb - 0x4b400000 + 127) << 23);
}

__device__ __forceinline__ void store_pair(float* C, size_t off, float v0, float v1) {
    *(float2*)(C + off) = make_float2(v0, v1);
}
__device__ __forceinline__ void store_pair(bf16* C, size_t off, float v0, float v1) {
    *(bf162*)(C + off) = __float22bfloat162_rn(make_float2(v0, v1));
}

// ---------------------------------------------------------------------------
// bf16 mma GEMM: C[M,N] = A[M,K] @ B[N,K]^T (+bias, relu, residual)
// 128x256 block tile, 128-half k-chunk (272B padded rows), 2-stage double
// buffer, 8 warps (2m x 4n), warp tile 64x64. ONE __syncthreads per k-chunk.
// ---------------------------------------------------------------------------
#define BM 128
#define BN 256
#define KCH 128
#define RSTR 272                     // 256B data + 16B pad
#define STAGE_B ((BM+BN)*RSTR)       // 104448 bytes
#define GEMM_SMEM (2*STAGE_B + 512)  // 209408

template<typename TO, bool RELU, bool RES, bool GATHER, bool SCATTER>
__global__ __launch_bounds__(256, 1) void gemm_mma(
    const bf16* __restrict__ A, const bf16* __restrict__ Bm,
    const float* __restrict__ bias, const float* __restrict__ Res,
    TO* __restrict__ C, int Nld, int K,
    int rowsPerExpert, long long bExpStride, int biasExpStride,
    const int* __restrict__ tokIdx, const float* __restrict__ gate)
{
    extern __shared__ char smem[];
    const uint32_t sb0 = smem_u32(smem);
    int* stok = (int*)(smem + 2*STAGE_B);
    const int tid = threadIdx.x;
    const int wid = tid >> 5, lane = tid & 31;
    const int j8 = lane & 7, gi = lane >> 3;
    const int lr = lane >> 2, lc = lane & 3;
    const int row0 = blockIdx.y * BM, col0 = blockIdx.x * BN;
    const int expert = row0 / rowsPerExpert;
    const bf16* Bexp = Bm + (long long)expert * bExpStride;
    const float* bb  = bias + (long long)expert * biasExpStride;
    const int m0 = (wid & 1) * 64, n0 = (wid >> 1) * 64;

    const bf16* Abase = GATHER ? A : A + (size_t)row0 * K;
    const bf16* Bbase = Bexp + (size_t)col0 * K;

    if (GATHER || SCATTER) {
        int v = 0;
        if (tid < BM) {
            int t = tokIdx[row0 + tid];
            stok[tid] = t;
            v = (t >= 0);
        }
        if (!__syncthreads_or(v)) return;   // whole tile empty -> no effect
    }

    const int arow = j8 + (gi & 1) * 8;
    const int aoff = (gi >> 1) * 16;
    const int brow = j8 + (gi >> 1) * 8;
    const int boff = (gi & 1) * 16;

    float acc[4][8][4];
#pragma unroll
    for (int mt = 0; mt < 4; mt++)
#pragma unroll
        for (int t = 0; t < 8; t++)
#pragma unroll
            for (int q = 0; q < 4; q++) acc[mt][t][q] = 0.f;

    const int nch = K / KCH;

    auto load_stage = [&](int s, int ch) {
        const uint32_t sa  = sb0 + (uint32_t)s * STAGE_B;
        const uint32_t sbm = sa + BM * RSTR;
        const bf16* Bcp = Bbase + ch * KCH;
#pragma unroll
        for (int q = 0; q < 8; q++) {          // A: 2048 segs of 16B
            int seg = tid + 256 * q;
            int r = seg >> 4, c = seg & 15;
            if (GATHER) {
                int t = stok[r];
                uint32_t sz = (t >= 0) ? 16u : 0u;
                const bf16* srcp = Abase + (size_t)(t >= 0 ? t : 0) * K + ch * KCH + c * 8;
                cp16z(sa + (uint32_t)(r * RSTR + c * 16), srcp, sz);
            } else {
                cp16(sa + (uint32_t)(r * RSTR + c * 16),
                     Abase + (size_t)r * K + ch * KCH + c * 8);
            }
        }
#pragma unroll
        for (int q = 0; q < 16; q++) {         // B: 4096 segs of 16B
            int seg = tid + 256 * q;
            int r = seg >> 4, c = seg & 15;
            cp16(sbm + (uint32_t)(r * RSTR + c * 16), Bcp + (size_t)r * K + c * 8);
        }
    };

    load_stage(0, 0);
    asm volatile("cp.async.commit_group;");

    for (int i = 0; i < nch; i++) {
        asm volatile("cp.async.wait_group 0;");
        __syncthreads();
        if (i + 1 < nch) load_stage((i + 1) & 1, i + 1);
        asm volatile("cp.async.commit_group;");

        const uint32_t sa  = sb0 + (uint32_t)(i & 1) * STAGE_B;
        const uint32_t sbm = sa + BM * RSTR;
#pragma unroll
        for (int kk = 0; kk < KCH/16; kk++) {
            uint32_t af[4][4];
#pragma unroll
            for (int mt = 0; mt < 4; mt++)
                ldm_x4(af[mt], sa + (uint32_t)((m0 + mt * 16 + arow) * RSTR + kk * 32 + aoff));
#pragma unroll
            for (int nt = 0; nt < 4; nt++) {
                uint32_t bfr[4];
                ldm_x4(bfr, sbm + (uint32_t)((n0 + nt * 16 + brow) * RSTR + kk * 32 + boff));
#pragma unroll
                for (int mt = 0; mt < 4; mt++) {
                    mma_bf16(acc[mt][nt * 2 + 0], af[mt], bfr[0], bfr[1]);
                    mma_bf16(acc[mt][nt * 2 + 1], af[mt], bfr[2], bfr[3]);
                }
            }
        }
    }

    // epilogue
#pragma unroll
    for (int mt = 0; mt < 4; mt++) {
        const int gr = row0 + m0 + mt * 16 + lr;
        int t0 = 0, t1 = 0;
        float g0 = 0.f, g1 = 0.f;
        if (SCATTER) {
            t0 = stok[m0 + mt * 16 + lr]; t1 = stok[m0 + mt * 16 + lr + 8];
            g0 = (t0 >= 0) ? gate[t0] : 0.f;
            g1 = (t1 >= 0) ? gate[t1] : 0.f;
        }
#pragma unroll
        for (int nt = 0; nt < 4; nt++) {
#pragma unroll
            for (int pr = 0; pr < 2; pr++) {
                const int gc = col0 + n0 + nt * 16 + pr * 8 + lc * 2;
                float* d = acc[mt][nt * 2 + pr];
                float b0 = bb[gc], b1 = bb[gc + 1];
                float v0 = d[0] + b0, v1 = d[1] + b1;
                float v2 = d[2] + b0, v3 = d[3] + b1;
                if (RELU) {
                    v0 = fmaxf(v0, 0.f); v1 = fmaxf(v1, 0.f);
                    v2 = fmaxf(v2, 0.f); v3 = fmaxf(v3, 0.f);
                }
                if (RES) {
                    float2 r0 = *(const float2*)(Res + (size_t)gr * Nld + gc);
                    float2 r1 = *(const float2*)(Res + (size_t)(gr + 8) * Nld + gc);
                    v0 += r0.x; v1 += r0.y; v2 += r1.x; v3 += r1.y;
                }
                if (SCATTER) {
                    if (t0 >= 0) {
                        float2 cur = *(float2*)((float*)C + (size_t)t0 * Nld + gc);
                        *(float2*)((float*)C + (size_t)t0 * Nld + gc) =
                            make_float2(cur.x + g0 * v0, cur.y + g0 * v1);
                    }
                    if (t1 >= 0) {
                        float2 cur = *(float2*)((float*)C + (size_t)t1 * Nld + gc);
                        *(float2*)((float*)C + (size_t)t1 * Nld + gc) =
                            make_float2(cur.x + g1 * v2, cur.y + g1 * v3);
                    }
                } else {
                    store_pair(C, (size_t)gr * Nld + gc, v0, v1);
                    store_pair(C, (size_t)(gr + 8) * Nld + gc, v2, v3);
                }
            }
        }
    }
}

// ---------------------------------------------------------------------------
// Flash attention, bf16 mma. 256 threads (8 warps), q-tile 128, k-tiles of 64.
// ONE __syncthreads per k-tile. Packed f32x2 softmax polynomial.
// ---------------------------------------------------------------------------
#define AT_SMEM (18432 + 9216*4 + 512)

__global__ __launch_bounds__(256, 2) void attn_mma(
    const bf16* __restrict__ qkv,
    const unsigned char* __restrict__ pad,
    bf16* __restrict__ outp)
{
    extern __shared__ char smem[];
    const uint32_t sQ  = smem_u32(smem);
    const uint32_t sK0 = sQ + 18432;
    const uint32_t sV0 = sK0 + 9216 * 2;
    float* mkp = (float*)(smem + 18432 + 9216 * 4);

    const int tid = threadIdx.x;
    const int wid = tid >> 5, lane = tid & 31;
    const int j8 = lane & 7, gi = lane >> 3;
    const int lc = lane & 3, lr = lane >> 2;
    const int bh = blockIdx.y, b = bh >> 4, h = bh & 15;
    const int q0 = blockIdx.x * 128;
    const size_t tokBase = (size_t)b * Sq;

    {
        const bf16* qb = qkv + (tokBase + q0) * 3072 + h * 64;
#pragma unroll
        for (int q = 0; q < 4; q++) {
            int seg = tid + 256 * q;
            int r = seg >> 3, c = seg & 7;
            cp16(sQ + (uint32_t)(r * 144 + c * 16), qb + (size_t)r * 3072 + c * 8);
        }
    }
    asm volatile("cp.async.commit_group;");

    auto prefetch = [&](int st, int kt) {
        const int k0 = kt * 64;
        const bf16* kb = qkv + (tokBase + k0) * 3072 + 1024 + h * 64;
        const bf16* vb = qkv + (tokBase + k0) * 3072 + 2048 + h * 64;
        const uint32_t sk = sK0 + (uint32_t)st * 9216, sv = sV0 + (uint32_t)st * 9216;
#pragma unroll
        for (int q = 0; q < 2; q++) {
            int seg = tid + 256 * q;
            int r = seg >> 3, c = seg & 7;
            cp16(sk + (uint32_t)(r * 144 + c * 16), kb + (size_t)r * 3072 + c * 8);
            cp16(sv + (uint32_t)(r * 144 + c * 16), vb + (size_t)r * 3072 + c * 8);
        }
        if (tid < 64) mkp[st * 64 + tid] = pad[tokBase + k0 + tid] ? -1e9f : 0.f;
    };

    prefetch(0, 0);
    asm volatile("cp.async.commit_group;");
    asm volatile("cp.async.wait_group 1;");
    __syncthreads();

    const int arow = j8 + (gi & 1) * 8, aoff = (gi >> 1) * 16;
    const int brow = j8 + (gi >> 1) * 8, boff = (gi & 1) * 16;

    uint32_t qa[4][4];
#pragma unroll
    for (int kd = 0; kd < 4; kd++)
        ldm_x4(qa[kd], sQ + (uint32_t)((wid * 16 + arow) * 144 + kd * 32 + aoff));

    float m0v = -1e30f, m1v = -1e30f, l0 = 0.f, l1 = 0.f;
    float o[8][4];
#pragma unroll
    for (int dt = 0; dt < 8; dt++)
#pragma unroll
        for (int q = 0; q < 4; q++) o[dt][q] = 0.f;

    for (int kt = 0; kt < Sq / 64; kt++) {
        const int st = kt & 1;
        asm volatile("cp.async.wait_group 0;");
        __syncthreads();
        if (kt + 1 < Sq / 64) prefetch(st ^ 1, kt + 1);
        asm volatile("cp.async.commit_group;");

        const uint32_t sk = sK0 + (uint32_t)st * 9216, sv = sV0 + (uint32_t)st * 9216;
        float s[8][4];
#pragma unroll
        for (int j = 0; j < 8; j++)
#pragma unroll
            for (int q = 0; q < 4; q++) s[j][q] = 0.f;

#pragma unroll
        for (int jp = 0; jp < 4; jp++) {
#pragma unroll
            for (int kd = 0; kd < 4; kd++) {
                uint32_t bfr[4];
                ldm_x4(bfr, sk + (uint32_t)((jp * 16 + brow) * 144 + kd * 32 + boff));
                mma_bf16(s[2 * jp],     qa[kd], bfr[0], bfr[1]);
                mma_bf16(s[2 * jp + 1], qa[kd], bfr[2], bfr[3]);
            }
        }

        float rmax0 = -1e30f, rmax1 = -1e30f;
#pragma unroll
        for (int j = 0; j < 8; j++) {
            float mka = mkp[st * 64 + j * 8 + 2 * lc];
            float mkb = mkp[st * 64 + j * 8 + 2 * lc + 1];
            s[j][0] = fmaf(s[j][0], 0.125f, mka);
            s[j][1] = fmaf(s[j][1], 0.125f, mkb);
            s[j][2] = fmaf(s[j][2], 0.125f, mka);
            s[j][3] = fmaf(s[j][3], 0.125f, mkb);
            rmax0 = fmaxf(rmax0, fmaxf(s[j][0], s[j][1]));
            rmax1 = fmaxf(rmax1, fmaxf(s[j][2], s[j][3]));
        }
        rmax0 = fmaxf(rmax0, __shfl_xor_sync(0xffffffffu, rmax0, 1));
        rmax0 = fmaxf(rmax0, __shfl_xor_sync(0xffffffffu, rmax0, 2));
        rmax1 = fmaxf(rmax1, __shfl_xor_sync(0xffffffffu, rmax1, 1));
        rmax1 = fmaxf(rmax1, __shfl_xor_sync(0xffffffffu, rmax1, 2));
        float nm0 = fmaxf(m0v, rmax0), nm1 = fmaxf(m1v, rmax1);
        float c0 = m0v - nm0, c1 = m1v - nm1;
        expp2(c0, c1);
        m0v = nm0; m1v = nm1;
        float rs0 = 0.f, rs1 = 0.f;
#pragma unroll
        for (int j = 0; j < 8; j++) {
            float a0 = s[j][0] - nm0, a1 = s[j][1] - nm0;
            float a2 = s[j][2] - nm1, a3 = s[j][3] - nm1;
            expp2(a0, a1);
            expp2(a2, a3);
            s[j][0] = a0; s[j][1] = a1; s[j][2] = a2; s[j][3] = a3;
            rs0 += a0 + a1;
            rs1 += a2 + a3;
        }
        rs0 += __shfl_xor_sync(0xffffffffu, rs0, 1);
        rs0 += __shfl_xor_sync(0xffffffffu, rs0, 2);
        rs1 += __shfl_xor_sync(0xffffffffu, rs1, 1);
        rs1 += __shfl_xor_sync(0xffffffffu, rs1, 2);
        l0 = l0 * c0 + rs0; l1 = l1 * c1 + rs1;
#pragma unroll
        for (int dt = 0; dt < 8; dt++) {
            o[dt][0] *= c0; o[dt][1] *= c0; o[dt][2] *= c1; o[dt][3] *= c1;
        }

        uint32_t pa[4][4];
#pragma unroll
        for (int t = 0; t < 4; t++) {
            pa[t][0] = pack_bf(s[2 * t][0],     s[2 * t][1]);
            pa[t][1] = pack_bf(s[2 * t][2],     s[2 * t][3]);
            pa[t][2] = pack_bf(s[2 * t + 1][0], s[2 * t + 1][1]);
            pa[t][3] = pack_bf(s[2 * t + 1][2], s[2 * t + 1][3]);
        }
#pragma unroll
        for (int t = 0; t < 4; t++) {
#pragma unroll
            for (int dp = 0; dp < 4; dp++) {
                uint32_t vf[4];
                ldm_x4t(vf, sv + (uint32_t)((t * 16 + arow) * 144 + dp * 32 + aoff));
                mma_bf16(o[2 * dp],     pa[t], vf[0], vf[1]);
                mma_bf16(o[2 * dp + 1], pa[t], vf[2], vf[3]);
            }
        }
    }

    float inv0 = 1.f / l0, inv1 = 1.f / l1;
    const int rg = q0 + wid * 16 + lr;
    bf16* ob = outp + (tokBase + rg) * Dm + h * 64;
#pragma unroll
    for (int dt = 0; dt < 8; dt++) {
        *(bf162*)(ob + dt * 8 + 2 * lc) =
            __float22bfloat162_rn(make_float2(o[dt][0] * inv0, o[dt][1] * inv0));
        *(bf162*)(ob + (size_t)8 * Dm + dt * 8 + 2 * lc) =
            __float22bfloat162_rn(make_float2(o[dt][2] * inv1, o[dt][3] * inv1));
    }
}

// ---------------------------------------------------------------------------
// LayerNorm (bf16 out, for LN1)
// ---------------------------------------------------------------------------
__global__ __launch_bounds__(256) void ln_kernel(const float* __restrict__ in,
                                                 const float* __restrict__ g,
                                                 const float* __restrict__ b,
                                                 bf16* __restrict__ out)
{
    int n = blockIdx.x, tid = threadIdx.x;
    float4 v = ((const float4*)(in + (size_t)n*Dm))[tid];
    float s  = v.x+v.y+v.z+v.w;
    float s2 = v.x*v.x+v.y*v.y+v.z*v.z+v.w*v.w;
    __shared__ float r1[256], r2[256];
    r1[tid]=s; r2[tid]=s2; __syncthreads();
    for (int st=128; st; st>>=1) {
        if (tid<st) { r1[tid]+=r1[tid+st]; r2[tid]+=r2[tid+st]; }
        __syncthreads();
    }
    float mean = r1[0]*(1.0f/Dm);
    float var  = r2[0]*(1.0f/Dm) - mean*mean;
    float rstd = rsqrtf(var + 1e-5f);
    float4 gg = ((const float4*)g)[tid];
    float4 bb = ((const float4*)b)[tid];
    float o0 = (v.x-mean)*rstd*gg.x + bb.x;
    float o1 = (v.y-mean)*rstd*gg.y + bb.y;
    float o2 = (v.z-mean)*rstd*gg.z + bb.z;
    float o3 = (v.w-mean)*rstd*gg.w + bb.w;
    size_t base = (size_t)n*Dm + tid*4;
    store_pair(out, base, o0, o1);
    store_pair(out, base + 2, o2, o3);
}

// ---------------------------------------------------------------------------
// LN2 + router fused (reads src1 values from `out` buffer)
// ---------------------------------------------------------------------------
__global__ __launch_bounds__(256) void ln2_router(const float* __restrict__ in,
                                                  const float* __restrict__ g,
                                                  const float* __restrict__ b,
                                                  bf16* __restrict__ outh,
                                                  const float* __restrict__ rw,
                                                  const float* __restrict__ rb,
                                                  const unsigned char* __restrict__ pad)
{
    int n = blockIdx.x, tid = threadIdx.x;
    __shared__ float r1[256], r2[256];
    __shared__ float xs[1024];
    __shared__ float lg[8];
    float4 v = ((const float4*)(in + (size_t)n*Dm))[tid];
    float s  = v.x+v.y+v.z+v.w;
    float s2 = v.x*v.x+v.y*v.y+v.z*v.z+v.w*v.w;
    r1[tid]=s; r2[tid]=s2; __syncthreads();
    for (int st=128; st; st>>=1) {
        if (tid<st) { r1[tid]+=r1[tid+st]; r2[tid]+=r2[tid+st]; }
        __syncthreads();
    }
    float mean = r1[0]*(1.0f/Dm);
    float var  = r2[0]*(1.0f/Dm) - mean*mean;
    float rstd = rsqrtf(var + 1e-5f);
    float4 gg = ((const float4*)g)[tid];
    float4 bb = ((const float4*)b)[tid];
    float4 o;
    o.x = (v.x-mean)*rstd*gg.x + bb.x;
    o.y = (v.y-mean)*rstd*gg.y + bb.y;
    o.z = (v.z-mean)*rstd*gg.z + bb.z;
    o.w = (v.w-mean)*rstd*gg.w + bb.w;
    bf162* hp = (bf162*)(outh + (size_t)n*Dm);
    hp[tid*2]   = __float22bfloat162_rn(make_float2(o.x, o.y));
    hp[tid*2+1] = __float22bfloat162_rn(make_float2(o.z, o.w));
    ((float4*)xs)[tid] = o;
    __syncthreads();
    int w = tid >> 5, lane = tid & 31;
    float acc = 0.f;
    for (int i = lane; i < 1024; i += 32) acc += xs[i] * rw[i*8 + w];
    for (int off=16; off; off>>=1) acc += __shfl_xor_sync(0xffffffffu, acc, off);
    if (lane == 0) lg[w] = acc + rb[w];
    __syncthreads();
    if (tid == 0) {
        float mx = lg[0]; int ei = 0;
        for (int e=1;e<8;e++) if (lg[e] > mx) { mx = lg[e]; ei = e; }
        float pr[8], se = 0.f;
        for (int e=0;e<8;e++) { pr[e] = expf(lg[e]-mx); se += pr[e]; }
        float inv = 1.f/se;
        bool valid = (pad[n] == 0);
        float tm = valid ? 1.f : 0.f;
        for (int e=0;e<8;e++) g_probs[n*8+e] = pr[e]*inv*tm;
        g_gate[n] = pr[ei]*inv;
        g_eidx[n] = ei;
        float lse = mx + logf(se);
        g_zterm[n] = lse*lse*tm;
    }
}

// ---------------------------------------------------------------------------
// Weight prep
// ---------------------------------------------------------------------------
__global__ __launch_bounds__(256) void bf16_copy(const float* __restrict__ in,
                                                 bf16* __restrict__ out, int n4)
{
    int i = blockIdx.x*256 + threadIdx.x;
    if (i < n4) {
        float4 v = ((const float4*)in)[i];
        ((bf162*)out)[i*2]   = __float22bfloat162_rn(make_float2(v.x, v.y));
        ((bf162*)out)[i*2+1] = __float22bfloat162_rn(make_float2(v.z, v.w));
    }
}

__global__ __launch_bounds__(256) void transpose_bf16(const float* __restrict__ in,
                                                      bf16* __restrict__ out,
                                                      int R, int Cc)
{
    __shared__ float t[32][33];
    int e = blockIdx.z;
    const float* ip = in  + (size_t)e*R*Cc;
    bf16* op        = out + (size_t)e*R*Cc;
    int c0 = blockIdx.x*32, r0 = blockIdx.y*32;
    int tx = threadIdx.x, ty = threadIdx.y;
#pragma unroll
    for (int j=0;j<32;j+=8)
        t[ty+j][tx] = ip[(size_t)(r0+ty+j)*Cc + c0+tx];
    __syncthreads();
#pragma unroll
    for (int j=0;j<32;j+=8)
        op[(size_t)(c0+ty+j)*R + r0+tx] = __float2bfloat16_rn(t[tx][ty+j]);
}

// ---------------------------------------------------------------------------
// Routing scan
// ---------------------------------------------------------------------------
__global__ __launch_bounds__(1024) void scan_kernel(const unsigned char* __restrict__ pad)
{
    __shared__ unsigned char sc[Ntok];
    __shared__ int base[8];
    int tid = threadIdx.x;
    for (int i = tid; i < SLOTS; i += 1024) g_tok[i] = -1;
    for (int i = tid; i < Ntok; i += 1024)
        sc[i] = (unsigned char)(g_eidx[i] | (pad[i] ? 0 : 16));
    if (tid < 8) base[tid] = 0;
    __syncthreads();
    if (tid < 32) {
        int lane = tid;
        for (int c = 0; c < Ntok/32; c++) {
            int i = c*32 + lane;
            int code = sc[i];
            int e = code & 7;
            bool valid = (code & 16) != 0;
            unsigned peers = __match_any_sync(0xffffffffu, e);
            unsigned vmask = __ballot_sync(0xffffffffu, valid);
            unsigned pv = peers & vmask;
            int myrank = __popc(pv & ((1u << lane) - 1u));
            int b0 = base[e];
            __syncwarp();
            int pos = b0 + myrank;
            bool keep = valid && (pos < CAP);
            if (keep) g_tok[e*CAP + pos] = i;
            if (valid && lane == (__ffs(pv) - 1)) base[e] = b0 + __popc(pv);
            __syncwarp();
        }
        if (lane < 8) g_cnt[lane] = base[lane];
    }
}

// ---------------------------------------------------------------------------
// Loss reduction
// ---------------------------------------------------------------------------
__global__ __launch_bounds__(256) void loss_kernel(const unsigned char* __restrict__ pad,
                                                   float* __restrict__ out)
{
    int tid = threadIdx.x;
    float zs = 0.f, ps[8];
    int cnt = 0;
#pragma unroll
    for (int e=0;e<8;e++) ps[e]=0.f;
    for (int n = tid; n < Ntok; n += 256) {
        if (pad[n] == 0) cnt++;
        zs += g_zterm[n];
#pragma unroll
        for (int e=0;e<8;e++) ps[e] += g_probs[n*8+e];
    }
    __shared__ float red[256];
    __shared__ float res[10];
    float vals[10];
    vals[0] = (float)cnt; vals[1] = zs;
    for (int e=0;e<8;e++) vals[2+e] = ps[e];
    for (int q=0;q<10;q++) {
        red[tid] = vals[q]; __syncthreads();
        for (int st=128; st; st>>=1) {
            if (tid < st) red[tid] += red[tid+st];
            __syncthreads();
        }
        if (tid == 0) res[q] = red[0];
        __syncthreads();
    }
    if (tid == 0) {
        float denom = fmaxf(res[0], 1.f);
        float lb = 0.f;
        for (int e=0;e<8;e++) lb += ((float)g_cnt[e]/denom) * (res[2+e]/denom);
        lb *= (float)Ee;
        out[(size_t)Ntok*Dm]     = lb;
        out[(size_t)Ntok*Dm + 1] = res[1]/denom;
    }
}

// ---------------------------------------------------------------------------
// Launch
// ---------------------------------------------------------------------------
extern "C" void kernel_launch(void* const* d_in, const int* in_sizes, int n_in,
                              void* d_out, int out_size)
{
    const float* src  = (const float*)d_in[0];
    const unsigned char* pad = (const unsigned char*)d_in[1];
    const float* ln1g = (const float*)d_in[2];
    const float* ln1b = (const float*)d_in[3];
    const float* ipw  = (const float*)d_in[4];
    const float* ipb  = (const float*)d_in[5];
    const float* opw  = (const float*)d_in[6];
    const float* opb  = (const float*)d_in[7];
    const float* ln2g = (const float*)d_in[8];
    const float* ln2b = (const float*)d_in[9];
    const float* rw   = (const float*)d_in[10];
    const float* rb   = (const float*)d_in[11];
    const float* w1   = (const float*)d_in[12];
    const float* b1   = (const float*)d_in[13];
    const float* w2   = (const float*)d_in[14];
    const float* b2   = (const float*)d_in[15];
    float* out = (float*)d_out;

    bf16 *xln, *qkv, *attn, *x2b, *hb, *ipw16, *opw16, *w1t, *w2t;
    float *gate;
    int *tok;
    cudaGetSymbolAddress((void**)&xln,  g_xln);
    cudaGetSymbolAddress((void**)&qkv,  g_qkv);
    cudaGetSymbolAddress((void**)&attn, g_attn);
    cudaGetSymbolAddress((void**)&x2b,  g_x2b);
    cudaGetSymbolAddress((void**)&hb,   g_hbuf);
    cudaGetSymbolAddress((void**)&ipw16, g_ipw16);
    cudaGetSymbolAddress((void**)&opw16, g_opw16);
    cudaGetSymbolAddress((void**)&w1t,  g_w1t);
    cudaGetSymbolAddress((void**)&w2t,  g_w2t);
    cudaGetSymbolAddress((void**)&tok,  g_tok);
    cudaGetSymbolAddress((void**)&gate, g_gate);

    static cudaStream_t s2 = nullptr;
    static cudaEvent_t ev0 = nullptr, evA = nullptr, ev1 = nullptr,
                       ev2 = nullptr, ev3 = nullptr;
    if (!s2) {
        cudaStreamCreateWithFlags(&s2, cudaStreamNonBlocking);
        cudaEventCreateWithFlags(&ev0, cudaEventDisableTiming);
        cudaEventCreateWithFlags(&evA, cudaEventDisableTiming);
        cudaEventCreateWithFlags(&ev1, cudaEventDisableTiming);
        cudaEventCreateWithFlags(&ev2, cudaEventDisableTiming);
        cudaEventCreateWithFlags(&ev3, cudaEventDisableTiming);
    }

    cudaFuncSetAttribute(attn_mma, cudaFuncAttributeMaxDynamicSharedMemorySize, AT_SMEM);
    cudaFuncSetAttribute(gemm_mma<bf16,false,false,false,false>, cudaFuncAttributeMaxDynamicSharedMemorySize, GEMM_SMEM);
    cudaFuncSetAttribute(gemm_mma<float,false,true,false,false>, cudaFuncAttributeMaxDynamicSharedMemorySize, GEMM_SMEM);
    cudaFuncSetAttribute(gemm_mma<bf16,true,false,true,false>,   cudaFuncAttributeMaxDynamicSharedMemorySize, GEMM_SMEM);
    cudaFuncSetAttribute(gemm_mma<float,false,false,false,true>, cudaFuncAttributeMaxDynamicSharedMemorySize, GEMM_SMEM);

    // Fork: ALL weight prep on side stream. ipw16 first (QKV gates on evA).
    cudaEventRecord(ev0, 0);
    cudaStreamWaitEvent(s2, ev0, 0);
    bf16_copy<<<(3*Dm*Dm/4 + 255)/256, 256, 0, s2>>>(ipw, ipw16, 3*Dm*Dm/4);
    cudaEventRecord(evA, s2);
    bf16_copy<<<(Dm*Dm/4 + 255)/256, 256, 0, s2>>>(opw, opw16, Dm*Dm/4);
    transpose_bf16<<<dim3(Ff/32, Dm/32, Ee), dim3(32,8), 0, s2>>>(w1, w1t, Dm, Ff);
    transpose_bf16<<<dim3(Dm/32, Ff/32, Ee), dim3(32,8), 0, s2>>>(w2, w2t, Ff, Dm);
    cudaEventRecord(ev1, s2);

    // Main stream: LN1 overlaps ipw copy.
    ln_kernel<<<Ntok, 256>>>(src, ln1g, ln1b, xln);
    cudaStreamWaitEvent(0, evA, 0);
    // 2. QKV -> bf16
    gemm_mma<bf16,false,false,false,false><<<dim3(3072/BN, Ntok/BM), 256, GEMM_SMEM>>>(
        xln, ipw16, ipb, nullptr, qkv, 3072, 1024, 1<<30, 0, 0, nullptr, nullptr);
    // 3. Attention -> bf16
    attn_mma<<<dim3(Sq/128, Bc*Hh), 256, AT_SMEM>>>(qkv, pad, attn);
    cudaStreamWaitEvent(0, ev1, 0);
    // 4. out_proj + residual(src) -> out directly
    gemm_mma<float,false,true,false,false><<<dim3(1024/BN, Ntok/BM), 256, GEMM_SMEM>>>(
        attn, opw16, opb, src, out, 1024, 1024, 1<<30, 0, 0, nullptr, nullptr);
    // 5. LN2 + router fused (reads src1 values from out)
    ln2_router<<<Ntok, 256>>>(out, ln2g, ln2b, x2b, rw, rb, pad);
    // 6. Scan
    scan_kernel<<<1, 1024>>>(pad);
    // Fork: loss on side stream.
    cudaEventRecord(ev2, 0);
    cudaStreamWaitEvent(s2, ev2, 0);
    loss_kernel<<<1, 256, 0, s2>>>(pad, out);
    cudaEventRecord(ev3, s2);
    // 7. FFN1 (gather, relu, empty-tile skip)
    gemm_mma<bf16,true,false,true,false><<<dim3(Ff/BN, SLOTS/BM), 256, GEMM_SMEM>>>(
        x2b, w1t, b1, nullptr, hb, Ff, 1024, CAP, (long long)Dm*Ff, Ff, tok, nullptr);
    // 8. FFN2 (scatter-add into out with gate, empty-tile skip)
    gemm_mma<float,false,false,false,true><<<dim3(Dm/BN, SLOTS/BM), 256, GEMM_SMEM>>>(
        hb, w2t, b2, nullptr, out, 1024, Ff, CAP, (long long)Ff*Dm, Dm, tok, gate);
    cudaStreamWaitEvent(0, ev3, 0);
}

// round 16
// speedup vs baseline: 1.0402x; 1.0016x over previous
#include <cuda_runtime.h>
#include <cuda_bf16.h>
#include <math.h>
#include <stdint.h>

// ---------------------------------------------------------------------------
// Problem constants
// ---------------------------------------------------------------------------
#define Bc   4
#define Sq   2048
#define Dm   1024
#define Hh   16
#define Ee   8
#define Ff   4096
#define Ntok (Bc*Sq)          // 8192
#define CAP  1280
#define SLOTS (Ee*CAP)        // 10240

typedef __nv_bfloat16 bf16;
typedef __nv_bfloat162 bf162;

// ---------------------------------------------------------------------------
// Device scratch
// ---------------------------------------------------------------------------
__device__ bf16  g_xln [Ntok*Dm];
__device__ bf16  g_qkv [Ntok*3*Dm];
__device__ bf16  g_attn[Ntok*Dm];
__device__ bf16  g_x2b [Ntok*Dm];
__device__ bf16  g_hbuf[(size_t)SLOTS*Ff];
__device__ float g_probs[Ntok*Ee];
__device__ float g_zterm[Ntok];
__device__ float g_gate [Ntok];
__device__ int   g_eidx [Ntok];
__device__ int   g_tok  [SLOTS];
__device__ int   g_cnt  [Ee];
// bf16 weight copies / transposes ([N,K] layouts)
__device__ bf16 g_ipw16[3*Dm*Dm];
__device__ bf16 g_opw16[Dm*Dm];
__device__ bf16 g_w1t [(size_t)Ee*Ff*Dm];   // [E][F][D]
__device__ bf16 g_w2t [(size_t)Ee*Dm*Ff];   // [E][D][F]

// ---------------------------------------------------------------------------
// Helpers
// ---------------------------------------------------------------------------
__device__ __forceinline__ uint32_t smem_u32(const void* p) {
    uint32_t a;
    asm("{ .reg .u64 t; cvta.to.shared.u64 t, %1; cvt.u32.u64 %0, t; }"
        : "=r"(a) : "l"(p));
    return a;
}
__device__ __forceinline__ void cp16(uint32_t dst, const void* src) {
    asm volatile("cp.async.cg.shared.global [%0], [%1], 16;" :: "r"(dst), "l"(src));
}
__device__ __forceinline__ void cp16z(uint32_t dst, const void* src, uint32_t sz) {
    asm volatile("cp.async.cg.shared.global [%0], [%1], 16, %2;"
                 :: "r"(dst), "l"(src), "r"(sz));
}
__device__ __forceinline__ void ldm_x4(uint32_t* r, uint32_t addr) {
    asm volatile("ldmatrix.sync.aligned.m8n8.x4.shared.b16 {%0,%1,%2,%3}, [%4];"
        : "=r"(r[0]), "=r"(r[1]), "=r"(r[2]), "=r"(r[3]) : "r"(addr));
}
__device__ __forceinline__ void ldm_x4t(uint32_t* r, uint32_t addr) {
    asm volatile("ldmatrix.sync.aligned.m8n8.x4.trans.shared.b16 {%0,%1,%2,%3}, [%4];"
        : "=r"(r[0]), "=r"(r[1]), "=r"(r[2]), "=r"(r[3]) : "r"(addr));
}
__device__ __forceinline__ void mma_bf16(float* d, const uint32_t* a,
                                         uint32_t b0, uint32_t b1) {
    asm volatile(
        "mma.sync.aligned.m16n8k16.row.col.f32.bf16.bf16.f32 "
        "{%0,%1,%2,%3}, {%4,%5,%6,%7}, {%8,%9}, {%0,%1,%2,%3};"
        : "+f"(d[0]), "+f"(d[1]), "+f"(d[2]), "+f"(d[3])
        : "r"(a[0]), "r"(a[1]), "r"(a[2]), "r"(a[3]), "r"(b0), "r"(b1));
}
__device__ __forceinline__ uint32_t pack_bf(float lo, float hi) {
    bf162 v = __float22bfloat162_rn(make_float2(lo, hi));
    return *(uint32_t*)&v;
}
// packed f32x2 primitives (per-lane IEEE-rn fp32, bit-identical to scalar)
__device__ __forceinline__ uint64_t pk2(float a, float b) {
    uint64_t r;
    asm("mov.b64 %0, {%1,%2};" : "=l"(r) : "f"(a), "f"(b));
    return r;
}
__device__ __forceinline__ void upk2(uint64_t v, float& a, float& b) {
    asm("mov.b64 {%0,%1}, %2;" : "=f"(a), "=f"(b) : "l"(v));
}
__device__ __forceinline__ uint64_t fma2(uint64_t a, uint64_t b, uint64_t c) {
    uint64_t d;
    asm("fma.rn.f32x2 %0, %1, %2, %3;" : "=l"(d) : "l"(a), "l"(b), "l"(c));
    return d;
}
__device__ __forceinline__ uint64_t mul2(uint64_t a, uint64_t b) {
    uint64_t d;
    asm("mul.rn.f32x2 %0, %1, %2;" : "=l"(d) : "l"(a), "l"(b));
    return d;
}
// fast exp via exp2 polynomial on the FMA pipe (MUFU is slow on B300)
__device__ __forceinline__ float expp(float x) {
    float y = fmaxf(x * 1.4426950408889634f, -120.f);
    float t = y + 12582912.f;
    int   e = __float_as_int(t);
    float r = t - 12582912.f;
    float f = y - r;
    float p = 1.3333558146e-3f;
    p = fmaf(p, f, 9.6181291076e-3f);
    p = fmaf(p, f, 5.5504108664e-2f);
    p = fmaf(p, f, 2.4022650696e-1f);
    p = fmaf(p, f, 6.9314718056e-1f);
    p = fmaf(p, f, 1.0f);
    float sc = __int_as_float((e - 0x4b400000 + 127) << 23);
    return p * sc;
}
// packed variant: identical per-lane IEEE-rn fp32 math, Horner on FFMA2.
__device__ __forceinline__ void expp2(float& xa, float& xb) {
    float ya = fmaxf(xa * 1.4426950408889634f, -120.f);
    float yb = fmaxf(xb * 1.4426950408889634f, -120.f);
    float ta = ya + 12582912.f;
    float tb = yb + 12582912.f;
    int ea = __float_as_int(ta);
    int eb = __float_as_int(tb);
    float fa = ya - (ta - 12582912.f);
    float fb = yb - (tb - 12582912.f);
    uint64_t f2 = pk2(fa, fb);
    uint64_t p2 = pk2(1.3333558146e-3f, 1.3333558146e-3f);
    p2 = fma2(p2, f2, pk2(9.6181291076e-3f, 9.6181291076e-3f));
    p2 = fma2(p2, f2, pk2(5.5504108664e-2f, 5.5504108664e-2f));
    p2 = fma2(p2, f2, pk2(2.4022650696e-1f, 2.4022650696e-1f));
    p2 = fma2(p2, f2, pk2(6.9314718056e-1f, 6.9314718056e-1f));
    p2 = fma2(p2, f2, pk2(1.0f, 1.0f));
    float pa, pb;
    upk2(p2, pa, pb);
    xa = pa * __int_as_float((ea - 0x4b400000 + 127) << 23);
    xb = pb * __int_as_float((eb - 0x4b400000 + 127) << 23);
}

__device__ __forceinline__ void store_pair(float* C, size_t off, float v0, float v1) {
    *(float2*)(C + off) = make_float2(v0, v1);
}
__device__ __forceinline__ void store_pair(bf16* C, size_t off, float v0, float v1) {
    *(bf162*)(C + off) = __float22bfloat162_rn(make_float2(v0, v1));
}

// ---------------------------------------------------------------------------
// bf16 mma GEMM: C[M,N] = A[M,K] @ B[N,K]^T (+bias, relu, residual)
// 128x256 block tile, 128-half k-chunk (272B padded rows), 2-stage double
// buffer, 8 warps (2m x 4n), warp tile 64x64. ONE __syncthreads per k-chunk.
// ---------------------------------------------------------------------------
#define BM 128
#define BN 256
#define KCH 128
#define RSTR 272                     // 256B data + 16B pad
#define STAGE_B ((BM+BN)*RSTR)       // 104448 bytes
#define GEMM_SMEM (2*STAGE_B + 512)  // 209408

template<typename TO, bool RELU, bool RES, bool GATHER, bool SCATTER>
__global__ __launch_bounds__(256, 1) void gemm_mma(
    const bf16* __restrict__ A, const bf16* __restrict__ Bm,
    const float* __restrict__ bias, const float* __restrict__ Res,
    TO* __restrict__ C, int Nld, int K,
    int rowsPerExpert, long long bExpStride, int biasExpStride,
    const int* __restrict__ tokIdx, const float* __restrict__ gate)
{
    extern __shared__ char smem[];
    const uint32_t sb0 = smem_u32(smem);
    int* stok = (int*)(smem + 2*STAGE_B);
    const int tid = threadIdx.x;
    const int wid = tid >> 5, lane = tid & 31;
    const int j8 = lane & 7, gi = lane >> 3;
    const int lr = lane >> 2, lc = lane & 3;
    const int row0 = blockIdx.y * BM, col0 = blockIdx.x * BN;
    const int expert = row0 / rowsPerExpert;
    const bf16* Bexp = Bm + (long long)expert * bExpStride;
    const float* bb  = bias + (long long)expert * biasExpStride;
    const int m0 = (wid & 1) * 64, n0 = (wid >> 1) * 64;

    const bf16* Abase = GATHER ? A : A + (size_t)row0 * K;
    const bf16* Bbase = Bexp + (size_t)col0 * K;

    if (GATHER || SCATTER) {
        int v = 0;
        if (tid < BM) {
            int t = tokIdx[row0 + tid];
            stok[tid] = t;
            v = (t >= 0);
        }
        if (!__syncthreads_or(v)) return;   // whole tile empty -> no effect
    }

    const int arow = j8 + (gi & 1) * 8;
    const int aoff = (gi >> 1) * 16;
    const int brow = j8 + (gi >> 1) * 8;
    const int boff = (gi & 1) * 16;

    float acc[4][8][4];
#pragma unroll
    for (int mt = 0; mt < 4; mt++)
#pragma unroll
        for (int t = 0; t < 8; t++)
#pragma unroll
            for (int q = 0; q < 4; q++) acc[mt][t][q] = 0.f;

    const int nch = K / KCH;

    auto load_stage = [&](int s, int ch) {
        const uint32_t sa  = sb0 + (uint32_t)s * STAGE_B;
        const uint32_t sbm = sa + BM * RSTR;
        const bf16* Bcp = Bbase + ch * KCH;
#pragma unroll
        for (int q = 0; q < 8; q++) {          // A: 2048 segs of 16B
            int seg = tid + 256 * q;
            int r = seg >> 4, c = seg & 15;
            if (GATHER) {
                int t = stok[r];
                uint32_t sz = (t >= 0) ? 16u : 0u;
                const bf16* srcp = Abase + (size_t)(t >= 0 ? t : 0) * K + ch * KCH + c * 8;
                cp16z(sa + (uint32_t)(r * RSTR + c * 16), srcp, sz);
            } else {
                cp16(sa + (uint32_t)(r * RSTR + c * 16),
                     Abase + (size_t)r * K + ch * KCH + c * 8);
            }
        }
#pragma unroll
        for (int q = 0; q < 16; q++) {         // B: 4096 segs of 16B
            int seg = tid + 256 * q;
            int r = seg >> 4, c = seg & 15;
            cp16(sbm + (uint32_t)(r * RSTR + c * 16), Bcp + (size_t)r * K + c * 8);
        }
    };

    load_stage(0, 0);
    asm volatile("cp.async.commit_group;");

    for (int i = 0; i < nch; i++) {
        asm volatile("cp.async.wait_group 0;");
        __syncthreads();
        if (i + 1 < nch) load_stage((i + 1) & 1, i + 1);
        asm volatile("cp.async.commit_group;");

        const uint32_t sa  = sb0 + (uint32_t)(i & 1) * STAGE_B;
        const uint32_t sbm = sa + BM * RSTR;
#pragma unroll
        for (int kk = 0; kk < KCH/16; kk++) {
            uint32_t af[4][4];
#pragma unroll
            for (int mt = 0; mt < 4; mt++)
                ldm_x4(af[mt], sa + (uint32_t)((m0 + mt * 16 + arow) * RSTR + kk * 32 + aoff));
#pragma unroll
            for (int nt = 0; nt < 4; nt++) {
                uint32_t bfr[4];
                ldm_x4(bfr, sbm + (uint32_t)((n0 + nt * 16 + brow) * RSTR + kk * 32 + boff));
#pragma unroll
                for (int mt = 0; mt < 4; mt++) {
                    mma_bf16(acc[mt][nt * 2 + 0], af[mt], bfr[0], bfr[1]);
                    mma_bf16(acc[mt][nt * 2 + 1], af[mt], bfr[2], bfr[3]);
                }
            }
        }
    }

    // epilogue
#pragma unroll
    for (int mt = 0; mt < 4; mt++) {
        const int gr = row0 + m0 + mt * 16 + lr;
        int t0 = 0, t1 = 0;
        float g0 = 0.f, g1 = 0.f;
        if (SCATTER) {
            t0 = stok[m0 + mt * 16 + lr]; t1 = stok[m0 + mt * 16 + lr + 8];
            g0 = (t0 >= 0) ? gate[t0] : 0.f;
            g1 = (t1 >= 0) ? gate[t1] : 0.f;
        }
#pragma unroll
        for (int nt = 0; nt < 4; nt++) {
#pragma unroll
            for (int pr = 0; pr < 2; pr++) {
                const int gc = col0 + n0 + nt * 16 + pr * 8 + lc * 2;
                float* d = acc[mt][nt * 2 + pr];
                float b0 = bb[gc], b1 = bb[gc + 1];
                float v0 = d[0] + b0, v1 = d[1] + b1;
                float v2 = d[2] + b0, v3 = d[3] + b1;
                if (RELU) {
                    v0 = fmaxf(v0, 0.f); v1 = fmaxf(v1, 0.f);
                    v2 = fmaxf(v2, 0.f); v3 = fmaxf(v3, 0.f);
                }
                if (RES) {
                    float2 r0 = *(const float2*)(Res + (size_t)gr * Nld + gc);
                    float2 r1 = *(const float2*)(Res + (size_t)(gr + 8) * Nld + gc);
                    v0 += r0.x; v1 += r0.y; v2 += r1.x; v3 += r1.y;
                }
                if (SCATTER) {
                    if (t0 >= 0) {
                        float2 cur = *(float2*)((float*)C + (size_t)t0 * Nld + gc);
                        *(float2*)((float*)C + (size_t)t0 * Nld + gc) =
                            make_float2(cur.x + g0 * v0, cur.y + g0 * v1);
                    }
                    if (t1 >= 0) {
                        float2 cur = *(float2*)((float*)C + (size_t)t1 * Nld + gc);
                        *(float2*)((float*)C + (size_t)t1 * Nld + gc) =
                            make_float2(cur.x + g1 * v2, cur.y + g1 * v3);
                    }
                } else {
                    store_pair(C, (size_t)gr * Nld + gc, v0, v1);
                    store_pair(C, (size_t)(gr + 8) * Nld + gc, v2, v3);
                }
            }
        }
    }
}

// ---------------------------------------------------------------------------
// Flash attention, bf16 mma. 256 threads (8 warps), q-tile 128, k-tiles of 64.
// ONE __syncthreads per k-tile. Fully-packed f32x2 softmax; rescale skipped
// (bit-identically) when the running max is unchanged warp-wide.
// ---------------------------------------------------------------------------
#define AT_SMEM (18432 + 9216*4 + 512)

__global__ __launch_bounds__(256, 2) void attn_mma(
    const bf16* __restrict__ qkv,
    const unsigned char* __restrict__ pad,
    bf16* __restrict__ outp)
{
    extern __shared__ char smem[];
    const uint32_t sQ  = smem_u32(smem);
    const uint32_t sK0 = sQ + 18432;
    const uint32_t sV0 = sK0 + 9216 * 2;
    float* mkp = (float*)(smem + 18432 + 9216 * 4);

    const int tid = threadIdx.x;
    const int wid = tid >> 5, lane = tid & 31;
    const int j8 = lane & 7, gi = lane >> 3;
    const int lc = lane & 3, lr = lane >> 2;
    const int bh = blockIdx.y, b = bh >> 4, h = bh & 15;
    const int q0 = blockIdx.x * 128;
    const size_t tokBase = (size_t)b * Sq;

    {
        const bf16* qb = qkv + (tokBase + q0) * 3072 + h * 64;
#pragma unroll
        for (int q = 0; q < 4; q++) {
            int seg = tid + 256 * q;
            int r = seg >> 3, c = seg & 7;
            cp16(sQ + (uint32_t)(r * 144 + c * 16), qb + (size_t)r * 3072 + c * 8);
        }
    }
    asm volatile("cp.async.commit_group;");

    auto prefetch = [&](int st, int kt) {
        const int k0 = kt * 64;
        const bf16* kb = qkv + (tokBase + k0) * 3072 + 1024 + h * 64;
        const bf16* vb = qkv + (tokBase + k0) * 3072 + 2048 + h * 64;
        const uint32_t sk = sK0 + (uint32_t)st * 9216, sv = sV0 + (uint32_t)st * 9216;
#pragma unroll
        for (int q = 0; q < 2; q++) {
            int seg = tid + 256 * q;
            int r = seg >> 3, c = seg & 7;
            cp16(sk + (uint32_t)(r * 144 + c * 16), kb + (size_t)r * 3072 + c * 8);
            cp16(sv + (uint32_t)(r * 144 + c * 16), vb + (size_t)r * 3072 + c * 8);
        }
        if (tid < 64) mkp[st * 64 + tid] = pad[tokBase + k0 + tid] ? -1e9f : 0.f;
    };

    prefetch(0, 0);
    asm volatile("cp.async.commit_group;");
    asm volatile("cp.async.wait_group 1;");
    __syncthreads();

    const int arow = j8 + (gi & 1) * 8, aoff = (gi >> 1) * 16;
    const int brow = j8 + (gi >> 1) * 8, boff = (gi & 1) * 16;

    uint32_t qa[4][4];
#pragma unroll
    for (int kd = 0; kd < 4; kd++)
        ldm_x4(qa[kd], sQ + (uint32_t)((wid * 16 + arow) * 144 + kd * 32 + aoff));

    float m0v = -1e30f, m1v = -1e30f, l0 = 0.f, l1 = 0.f;
    float o[8][4];
#pragma unroll
    for (int dt = 0; dt < 8; dt++)
#pragma unroll
        for (int q = 0; q < 4; q++) o[dt][q] = 0.f;

    const uint64_t scale2 = pk2(0.125f, 0.125f);

    for (int kt = 0; kt < Sq / 64; kt++) {
        const int st = kt & 1;
        asm volatile("cp.async.wait_group 0;");
        __syncthreads();
        if (kt + 1 < Sq / 64) prefetch(st ^ 1, kt + 1);
        asm volatile("cp.async.commit_group;");

        const uint32_t sk = sK0 + (uint32_t)st * 9216, sv = sV0 + (uint32_t)st * 9216;
        float s[8][4];
#pragma unroll
        for (int j = 0; j < 8; j++)
#pragma unroll
            for (int q = 0; q < 4; q++) s[j][q] = 0.f;

#pragma unroll
        for (int jp = 0; jp < 4; jp++) {
#pragma unroll
            for (int kd = 0; kd < 4; kd++) {
                uint32_t bfr[4];
                ldm_x4(bfr, sk + (uint32_t)((jp * 16 + brow) * 144 + kd * 32 + boff));
                mma_bf16(s[2 * jp],     qa[kd], bfr[0], bfr[1]);
                mma_bf16(s[2 * jp + 1], qa[kd], bfr[2], bfr[3]);
            }
        }

        // packed scale+mask, then row max
        float rmax0 = -1e30f, rmax1 = -1e30f;
#pragma unroll
        for (int j = 0; j < 8; j++) {
            const uint64_t mk2 = pk2(mkp[st * 64 + j * 8 + 2 * lc],
                                     mkp[st * 64 + j * 8 + 2 * lc + 1]);
            uint64_t v01 = fma2(pk2(s[j][0], s[j][1]), scale2, mk2);
            uint64_t v23 = fma2(pk2(s[j][2], s[j][3]), scale2, mk2);
            upk2(v01, s[j][0], s[j][1]);
            upk2(v23, s[j][2], s[j][3]);
            rmax0 = fmaxf(rmax0, fmaxf(s[j][0], s[j][1]));
            rmax1 = fmaxf(rmax1, fmaxf(s[j][2], s[j][3]));
        }
        rmax0 = fmaxf(rmax0, __shfl_xor_sync(0xffffffffu, rmax0, 1));
        rmax0 = fmaxf(rmax0, __shfl_xor_sync(0xffffffffu, rmax0, 2));
        rmax1 = fmaxf(rmax1, __shfl_xor_sync(0xffffffffu, rmax1, 1));
        rmax1 = fmaxf(rmax1, __shfl_xor_sync(0xffffffffu, rmax1, 2));
        float nm0 = fmaxf(m0v, rmax0), nm1 = fmaxf(m1v, rmax1);
        // exact: if neither row max moved, c0 == c1 == 1.0f -> skip rescale
        bool upd = (nm0 > m0v) || (nm1 > m1v);
        bool anyupd = __any_sync(0xffffffffu, upd);
        float c0 = 1.f, c1 = 1.f;
        if (anyupd) {
            c0 = m0v - nm0; c1 = m1v - nm1;
            expp2(c0, c1);
        }
        m0v = nm0; m1v = nm1;
        float rs0 = 0.f, rs1 = 0.f;
#pragma unroll
        for (int j = 0; j < 8; j++) {
            float a0 = s[j][0] - nm0, a1 = s[j][1] - nm0;
            float a2 = s[j][2] - nm1, a3 = s[j][3] - nm1;
            expp2(a0, a1);
            expp2(a2, a3);
            s[j][0] = a0; s[j][1] = a1; s[j][2] = a2; s[j][3] = a3;
            rs0 += a0 + a1;
            rs1 += a2 + a3;
        }
        rs0 += __shfl_xor_sync(0xffffffffu, rs0, 1);
        rs0 += __shfl_xor_sync(0xffffffffu, rs0, 2);
        rs1 += __shfl_xor_sync(0xffffffffu, rs1, 1);
        rs1 += __shfl_xor_sync(0xffffffffu, rs1, 2);
        if (anyupd) {
            l0 = fmaf(l0, c0, rs0); l1 = fmaf(l1, c1, rs1);
            const uint64_t c02 = pk2(c0, c0), c12 = pk2(c1, c1);
#pragma unroll
            for (int dt = 0; dt < 8; dt++) {
                uint64_t p01 = mul2(pk2(o[dt][0], o[dt][1]), c02);
                uint64_t p23 = mul2(pk2(o[dt][2], o[dt][3]), c12);
                upk2(p01, o[dt][0], o[dt][1]);
                upk2(p23, o[dt][2], o[dt][3]);
            }
        } else {
            l0 += rs0; l1 += rs1;
        }

        uint32_t pa[4][4];
#pragma unroll
        for (int t = 0; t < 4; t++) {
            pa[t][0] = pack_bf(s[2 * t][0],     s[2 * t][1]);
            pa[t][1] = pack_bf(s[2 * t][2],     s[2 * t][3]);
            pa[t][2] = pack_bf(s[2 * t + 1][0], s[2 * t + 1][1]);
            pa[t][3] = pack_bf(s[2 * t + 1][2], s[2 * t + 1][3]);
        }
#pragma unroll
        for (int t = 0; t < 4; t++) {
#pragma unroll
            for (int dp = 0; dp < 4; dp++) {
                uint32_t vf[4];
                ldm_x4t(vf, sv + (uint32_t)((t * 16 + arow) * 144 + dp * 32 + aoff));
                mma_bf16(o[2 * dp],     pa[t], vf[0], vf[1]);
                mma_bf16(o[2 * dp + 1], pa[t], vf[2], vf[3]);
            }
        }
    }

    float inv0 = 1.f / l0, inv1 = 1.f / l1;
    const int rg = q0 + wid * 16 + lr;
    bf16* ob = outp + (tokBase + rg) * Dm + h * 64;
#pragma unroll
    for (int dt = 0; dt < 8; dt++) {
        *(bf162*)(ob + dt * 8 + 2 * lc) =
            __float22bfloat162_rn(make_float2(o[dt][0] * inv0, o[dt][1] * inv0));
        *(bf162*)(ob + (size_t)8 * Dm + dt * 8 + 2 * lc) =
            __float22bfloat162_rn(make_float2(o[dt][2] * inv1, o[dt][3] * inv1));
    }
}

// ---------------------------------------------------------------------------
// LayerNorm (bf16 out, for LN1)
// ---------------------------------------------------------------------------
__global__ __launch_bounds__(256) void ln_kernel(const float* __restrict__ in,
                                                 const float* __restrict__ g,
                                                 const float* __restrict__ b,
                                                 bf16* __restrict__ out)
{
    int n = blockIdx.x, tid = threadIdx.x;
    float4 v = ((const float4*)(in + (size_t)n*Dm))[tid];
    float s  = v.x+v.y+v.z+v.w;
    float s2 = v.x*v.x+v.y*v.y+v.z*v.z+v.w*v.w;
    __shared__ float r1[256], r2[256];
    r1[tid]=s; r2[tid]=s2; __syncthreads();
    for (int st=128; st; st>>=1) {
        if (tid<st) { r1[tid]+=r1[tid+st]; r2[tid]+=r2[tid+st]; }
        __syncthreads();
    }
    float mean = r1[0]*(1.0f/Dm);
    float var  = r2[0]*(1.0f/Dm) - mean*mean;
    float rstd = rsqrtf(var + 1e-5f);
    float4 gg = ((const float4*)g)[tid];
    float4 bb = ((const float4*)b)[tid];
    float o0 = (v.x-mean)*rstd*gg.x + bb.x;
    float o1 = (v.y-mean)*rstd*gg.y + bb.y;
    float o2 = (v.z-mean)*rstd*gg.z + bb.z;
    float o3 = (v.w-mean)*rstd*gg.w + bb.w;
    size_t base = (size_t)n*Dm + tid*4;
    store_pair(out, base, o0, o1);
    store_pair(out, base + 2, o2, o3);
}

// ---------------------------------------------------------------------------
// LN2 + router fused (reads src1 values from `out` buffer)
// ---------------------------------------------------------------------------
__global__ __launch_bounds__(256) void ln2_router(const float* __restrict__ in,
                                                  const float* __restrict__ g,
                                                  const float* __restrict__ b,
                                                  bf16* __restrict__ outh,
                                                  const float* __restrict__ rw,
                                                  const float* __restrict__ rb,
                                                  const unsigned char* __restrict__ pad)
{
    int n = blockIdx.x, tid = threadIdx.x;
    __shared__ float r1[256], r2[256];
    __shared__ float xs[1024];
    __shared__ float lg[8];
    float4 v = ((const float4*)(in + (size_t)n*Dm))[tid];
    float s  = v.x+v.y+v.z+v.w;
    float s2 = v.x*v.x+v.y*v.y+v.z*v.z+v.w*v.w;
    r1[tid]=s; r2[tid]=s2; __syncthreads();
    for (int st=128; st; st>>=1) {
        if (tid<st) { r1[tid]+=r1[tid+st]; r2[tid]+=r2[tid+st]; }
        __syncthreads();
    }
    float mean = r1[0]*(1.0f/Dm);
    float var  = r2[0]*(1.0f/Dm) - mean*mean;
    float rstd = rsqrtf(var + 1e-5f);
    float4 gg = ((const float4*)g)[tid];
    float4 bb = ((const float4*)b)[tid];
    float4 o;
    o.x = (v.x-mean)*rstd*gg.x + bb.x;
    o.y = (v.y-mean)*rstd*gg.y + bb.y;
    o.z = (v.z-mean)*rstd*gg.z + bb.z;
    o.w = (v.w-mean)*rstd*gg.w + bb.w;
    bf162* hp = (bf162*)(outh + (size_t)n*Dm);
    hp[tid*2]   = __float22bfloat162_rn(make_float2(o.x, o.y));
    hp[tid*2+1] = __float22bfloat162_rn(make_float2(o.z, o.w));
    ((float4*)xs)[tid] = o;
    __syncthreads();
    int w = tid >> 5, lane = tid & 31;
    float acc = 0.f;
    for (int i = lane; i < 1024; i += 32) acc += xs[i] * rw[i*8 + w];
    for (int off=16; off; off>>=1) acc += __shfl_xor_sync(0xffffffffu, acc, off);
    if (lane == 0) lg[w] = acc + rb[w];
    __syncthreads();
    if (tid == 0) {
        float mx = lg[0]; int ei = 0;
        for (int e=1;e<8;e++) if (lg[e] > mx) { mx = lg[e]; ei = e; }
        float pr[8], se = 0.f;
        for (int e=0;e<8;e++) { pr[e] = expf(lg[e]-mx); se += pr[e]; }
        float inv = 1.f/se;
        bool valid = (pad[n] == 0);
        float tm = valid ? 1.f : 0.f;
        for (int e=0;e<8;e++) g_probs[n*8+e] = pr[e]*inv*tm;
        g_gate[n] = pr[ei]*inv;
        g_eidx[n] = ei;
        float lse = mx + logf(se);
        g_zterm[n] = lse*lse*tm;
    }
}

// ---------------------------------------------------------------------------
// Weight prep
// ---------------------------------------------------------------------------
__global__ __launch_bounds__(256) void bf16_copy(const float* __restrict__ in,
                                                 bf16* __restrict__ out, int n4)
{
    int i = blockIdx.x*256 + threadIdx.x;
    if (i < n4) {
        float4 v = ((const float4*)in)[i];
        ((bf162*)out)[i*2]   = __float22bfloat162_rn(make_float2(v.x, v.y));
        ((bf162*)out)[i*2+1] = __float22bfloat162_rn(make_float2(v.z, v.w));
    }
}

__global__ __launch_bounds__(256) void transpose_bf16(const float* __restrict__ in,
                                                      bf16* __restrict__ out,
                                                      int R, int Cc)
{
    __shared__ float t[32][33];
    int e = blockIdx.z;
    const float* ip = in  + (size_t)e*R*Cc;
    bf16* op        = out + (size_t)e*R*Cc;
    int c0 = blockIdx.x*32, r0 = blockIdx.y*32;
    int tx = threadIdx.x, ty = threadIdx.y;
#pragma unroll
    for (int j=0;j<32;j+=8)
        t[ty+j][tx] = ip[(size_t)(r0+ty+j)*Cc + c0+tx];
    __syncthreads();
#pragma unroll
    for (int j=0;j<32;j+=8)
        op[(size_t)(c0+ty+j)*R + r0+tx] = __float2bfloat16_rn(t[tx][ty+j]);
}

// ---------------------------------------------------------------------------
// Routing scan
// ---------------------------------------------------------------------------
__global__ __launch_bounds__(1024) void scan_kernel(const unsigned char* __restrict__ pad)
{
    __shared__ unsigned char sc[Ntok];
    __shared__ int base[8];
    int tid = threadIdx.x;
    for (int i = tid; i < SLOTS; i += 1024) g_tok[i] = -1;
    for (int i = tid; i < Ntok; i += 1024)
        sc[i] = (unsigned char)(g_eidx[i] | (pad[i] ? 0 : 16));
    if (tid < 8) base[tid] = 0;
    __syncthreads();
    if (tid < 32) {
        int lane = tid;
        for (int c = 0; c < Ntok/32; c++) {
            int i = c*32 + lane;
            int code = sc[i];
            int e = code & 7;
            bool valid = (code & 16) != 0;
            unsigned peers = __match_any_sync(0xffffffffu, e);
            unsigned vmask = __ballot_sync(0xffffffffu, valid);
            unsigned pv = peers & vmask;
            int myrank = __popc(pv & ((1u << lane) - 1u));
            int b0 = base[e];
            __syncwarp();
            int pos = b0 + myrank;
            bool keep = valid && (pos < CAP);
            if (keep) g_tok[e*CAP + pos] = i;
            if (valid && lane == (__ffs(pv) - 1)) base[e] = b0 + __popc(pv);
            __syncwarp();
        }
        if (lane < 8) g_cnt[lane] = base[lane];
    }
}

// ---------------------------------------------------------------------------
// Loss reduction
// ---------------------------------------------------------------------------
__global__ __launch_bounds__(256) void loss_kernel(const unsigned char* __restrict__ pad,
                                                   float* __restrict__ out)
{
    int tid = threadIdx.x;
    float zs = 0.f, ps[8];
    int cnt = 0;
#pragma unroll
    for (int e=0;e<8;e++) ps[e]=0.f;
    for (int n = tid; n < Ntok; n += 256) {
        if (pad[n] == 0) cnt++;
        zs += g_zterm[n];
#pragma unroll
        for (int e=0;e<8;e++) ps[e] += g_probs[n*8+e];
    }
    __shared__ float red[256];
    __shared__ float res[10];
    float vals[10];
    vals[0] = (float)cnt; vals[1] = zs;
    for (int e=0;e<8;e++) vals[2+e] = ps[e];
    for (int q=0;q<10;q++) {
        red[tid] = vals[q]; __syncthreads();
        for (int st=128; st; st>>=1) {
            if (tid < st) red[tid] += red[tid+st];
            __syncthreads();
        }
        if (tid == 0) res[q] = red[0];
        __syncthreads();
    }
    if (tid == 0) {
        float denom = fmaxf(res[0], 1.f);
        float lb = 0.f;
        for (int e=0;e<8;e++) lb += ((float)g_cnt[e]/denom) * (res[2+e]/denom);
        lb *= (float)Ee;
        out[(size_t)Ntok*Dm]     = lb;
        out[(size_t)Ntok*Dm + 1] = res[1]/denom;
    }
}

// ---------------------------------------------------------------------------
// Launch
// ---------------------------------------------------------------------------
extern "C" void kernel_launch(void* const* d_in, const int* in_sizes, int n_in,
                              void* d_out, int out_size)
{
    const float* src  = (const float*)d_in[0];
    const unsigned char* pad = (const unsigned char*)d_in[1];
    const float* ln1g = (const float*)d_in[2];
    const float* ln1b = (const float*)d_in[3];
    const float* ipw  = (const float*)d_in[4];
    const float* ipb  = (const float*)d_in[5];
    const float* opw  = (const float*)d_in[6];
    const float* opb  = (const float*)d_in[7];
    const float* ln2g = (const float*)d_in[8];
    const float* ln2b = (const float*)d_in[9];
    const float* rw   = (const float*)d_in[10];
    const float* rb   = (const float*)d_in[11];
    const float* w1   = (const float*)d_in[12];
    const float* b1   = (const float*)d_in[13];
    const float* w2   = (const float*)d_in[14];
    const float* b2   = (const float*)d_in[15];
    float* out = (float*)d_out;

    bf16 *xln, *qkv, *attn, *x2b, *hb, *ipw16, *opw16, *w1t, *w2t;
    float *gate;
    int *tok;
    cudaGetSymbolAddress((void**)&xln,  g_xln);
    cudaGetSymbolAddress((void**)&qkv,  g_qkv);
    cudaGetSymbolAddress((void**)&attn, g_attn);
    cudaGetSymbolAddress((void**)&x2b,  g_x2b);
    cudaGetSymbolAddress((void**)&hb,   g_hbuf);
    cudaGetSymbolAddress((void**)&ipw16, g_ipw16);
    cudaGetSymbolAddress((void**)&opw16, g_opw16);
    cudaGetSymbolAddress((void**)&w1t,  g_w1t);
    cudaGetSymbolAddress((void**)&w2t,  g_w2t);
    cudaGetSymbolAddress((void**)&tok,  g_tok);
    cudaGetSymbolAddress((void**)&gate, g_gate);

    static cudaStream_t s2 = nullptr;
    static cudaEvent_t ev0 = nullptr, evA = nullptr, ev1 = nullptr,
                       ev2 = nullptr, ev3 = nullptr;
    if (!s2) {
        cudaStreamCreateWithFlags(&s2, cudaStreamNonBlocking);
        cudaEventCreateWithFlags(&ev0, cudaEventDisableTiming);
        cudaEventCreateWithFlags(&evA, cudaEventDisableTiming);
        cudaEventCreateWithFlags(&ev1, cudaEventDisableTiming);
        cudaEventCreateWithFlags(&ev2, cudaEventDisableTiming);
        cudaEventCreateWithFlags(&ev3, cudaEventDisableTiming);
    }

    cudaFuncSetAttribute(attn_mma, cudaFuncAttributeMaxDynamicSharedMemorySize, AT_SMEM);
    cudaFuncSetAttribute(gemm_mma<bf16,false,false,false,false>, cudaFuncAttributeMaxDynamicSharedMemorySize, GEMM_SMEM);
    cudaFuncSetAttribute(gemm_mma<float,false,true,false,false>, cudaFuncAttributeMaxDynamicSharedMemorySize, GEMM_SMEM);
    cudaFuncSetAttribute(gemm_mma<bf16,true,false,true,false>,   cudaFuncAttributeMaxDynamicSharedMemorySize, GEMM_SMEM);
    cudaFuncSetAttribute(gemm_mma<float,false,false,false,true>, cudaFuncAttributeMaxDynamicSharedMemorySize, GEMM_SMEM);

    // Fork: ALL weight prep on side stream. ipw16 first (QKV gates on evA).
    cudaEventRecord(ev0, 0);
    cudaStreamWaitEvent(s2, ev0, 0);
    bf16_copy<<<(3*Dm*Dm/4 + 255)/256, 256, 0, s2>>>(ipw, ipw16, 3*Dm*Dm/4);
    cudaEventRecord(evA, s2);
    bf16_copy<<<(Dm*Dm/4 + 255)/256, 256, 0, s2>>>(opw, opw16, Dm*Dm/4);
    transpose_bf16<<<dim3(Ff/32, Dm/32, Ee), dim3(32,8), 0, s2>>>(w1, w1t, Dm, Ff);
    transpose_bf16<<<dim3(Dm/32, Ff/32, Ee), dim3(32,8), 0, s2>>>(w2, w2t, Ff, Dm);
    cudaEventRecord(ev1, s2);

    // Main stream: LN1 overlaps ipw copy.
    ln_kernel<<<Ntok, 256>>>(src, ln1g, ln1b, xln);
    cudaStreamWaitEvent(0, evA, 0);
    // 2. QKV -> bf16
    gemm_mma<bf16,false,false,false,false><<<dim3(3072/BN, Ntok/BM), 256, GEMM_SMEM>>>(
        xln, ipw16, ipb, nullptr, qkv, 3072, 1024, 1<<30, 0, 0, nullptr, nullptr);
    // 3. Attention -> bf16
    attn_mma<<<dim3(Sq/128, Bc*Hh), 256, AT_SMEM>>>(qkv, pad, attn);
    cudaStreamWaitEvent(0, ev1, 0);
    // 4. out_proj + residual(src) -> out directly
    gemm_mma<float,false,true,false,false><<<dim3(1024/BN, Ntok/BM), 256, GEMM_SMEM>>>(
        attn, opw16, opb, src, out, 1024, 1024, 1<<30, 0, 0, nullptr, nullptr);
    // 5. LN2 + router fused (reads src1 values from out)
    ln2_router<<<Ntok, 256>>>(out, ln2g, ln2b, x2b, rw, rb, pad);
    // 6. Scan
    scan_kernel<<<1, 1024>>>(pad);
    // Fork: loss on side stream.
    cudaEventRecord(ev2, 0);
    cudaStreamWaitEvent(s2, ev2, 0);
    loss_kernel<<<1, 256, 0, s2>>>(pad, out);
    cudaEventRecord(ev3, s2);
    // 7. FFN1 (gather, relu, empty-tile skip)
    gemm_mma<bf16,true,false,true,false><<<dim3(Ff/BN, SLOTS/BM), 256, GEMM_SMEM>>>(
        x2b, w1t, b1, nullptr, hb, Ff, 1024, CAP, (long long)Dm*Ff, Ff, tok, nullptr);
    // 8. FFN2 (scatter-add into out with gate, empty-tile skip)
    gemm_mma<float,false,false,false,true><<<dim3(Dm/BN, SLOTS/BM), 256, GEMM_SMEM>>>(
        hb, w2t, b2, nullptr, out, 1024, Ff, CAP, (long long)Ff*Dm, Dm, tok, gate);
    cudaStreamWaitEvent(0, ev3, 0);
}

// round 17
// speedup vs baseline: 1.1144x; 1.0714x over previous
#include <cuda_runtime.h>
#include <cuda_bf16.h>
#include <math.h>
#include <stdint.h>

// ---------------------------------------------------------------------------
// Problem constants
// ---------------------------------------------------------------------------
#define Bc   4
#define Sq   2048
#define Dm   1024
#define Hh   16
#define Ee   8
#define Ff   4096
#define Ntok (Bc*Sq)          // 8192
#define CAP  1280
#define SLOTS (Ee*CAP)        // 10240

typedef __nv_bfloat16 bf16;
typedef __nv_bfloat162 bf162;

// ---------------------------------------------------------------------------
// Device scratch
// ---------------------------------------------------------------------------
__device__ bf16  g_xln [Ntok*Dm];
__device__ bf16  g_qkv [Ntok*3*Dm];
__device__ bf16  g_attn[Ntok*Dm];
__device__ bf16  g_x2b [Ntok*Dm];
__device__ bf16  g_hbuf[(size_t)SLOTS*Ff];
__device__ float g_probs[Ntok*Ee];
__device__ float g_zterm[Ntok];
__device__ float g_gate [Ntok];
__device__ int   g_eidx [Ntok];
__device__ int   g_tok  [SLOTS];
__device__ int   g_cnt  [Ee];
// bf16 weight copies / transposes ([N,K] layouts)
__device__ bf16 g_ipw16[3*Dm*Dm];
__device__ bf16 g_opw16[Dm*Dm];
__device__ bf16 g_w1t [(size_t)Ee*Ff*Dm];   // [E][F][D]
__device__ bf16 g_w2t [(size_t)Ee*Dm*Ff];   // [E][D][F]

// ---------------------------------------------------------------------------
// Helpers
// ---------------------------------------------------------------------------
__device__ __forceinline__ uint32_t smem_u32(const void* p) {
    uint32_t a;
    asm("{ .reg .u64 t; cvta.to.shared.u64 t, %1; cvt.u32.u64 %0, t; }"
        : "=r"(a) : "l"(p));
    return a;
}
__device__ __forceinline__ void cp16(uint32_t dst, const void* src) {
    asm volatile("cp.async.cg.shared.global [%0], [%1], 16;" :: "r"(dst), "l"(src));
}
__device__ __forceinline__ void cp16z(uint32_t dst, const void* src, uint32_t sz) {
    asm volatile("cp.async.cg.shared.global [%0], [%1], 16, %2;"
                 :: "r"(dst), "l"(src), "r"(sz));
}
__device__ __forceinline__ void ldm_x4(uint32_t* r, uint32_t addr) {
    asm volatile("ldmatrix.sync.aligned.m8n8.x4.shared.b16 {%0,%1,%2,%3}, [%4];"
        : "=r"(r[0]), "=r"(r[1]), "=r"(r[2]), "=r"(r[3]) : "r"(addr));
}
__device__ __forceinline__ void ldm_x4t(uint32_t* r, uint32_t addr) {
    asm volatile("ldmatrix.sync.aligned.m8n8.x4.trans.shared.b16 {%0,%1,%2,%3}, [%4];"
        : "=r"(r[0]), "=r"(r[1]), "=r"(r[2]), "=r"(r[3]) : "r"(addr));
}
__device__ __forceinline__ void mma_bf16(float* d, const uint32_t* a,
                                         uint32_t b0, uint32_t b1) {
    asm volatile(
        "mma.sync.aligned.m16n8k16.row.col.f32.bf16.bf16.f32 "
        "{%0,%1,%2,%3}, {%4,%5,%6,%7}, {%8,%9}, {%0,%1,%2,%3};"
        : "+f"(d[0]), "+f"(d[1]), "+f"(d[2]), "+f"(d[3])
        : "r"(a[0]), "r"(a[1]), "r"(a[2]), "r"(a[3]), "r"(b0), "r"(b1));
}
__device__ __forceinline__ uint32_t pack_bf(float lo, float hi) {
    bf162 v = __float22bfloat162_rn(make_float2(lo, hi));
    return *(uint32_t*)&v;
}
// packed f32x2 primitives (per-lane IEEE-rn fp32, bit-identical to scalar)
__device__ __forceinline__ uint64_t pk2(float a, float b) {
    uint64_t r;
    asm("mov.b64 %0, {%1,%2};" : "=l"(r) : "f"(a), "f"(b));
    return r;
}
__device__ __forceinline__ void upk2(uint64_t v, float& a, float& b) {
    asm("mov.b64 {%0,%1}, %2;" : "=f"(a), "=f"(b) : "l"(v));
}
__device__ __forceinline__ uint64_t fma2(uint64_t a, uint64_t b, uint64_t c) {
    uint64_t d;
    asm("fma.rn.f32x2 %0, %1, %2, %3;" : "=l"(d) : "l"(a), "l"(b), "l"(c));
    return d;
}
__device__ __forceinline__ uint64_t mul2(uint64_t a, uint64_t b) {
    uint64_t d;
    asm("mul.rn.f32x2 %0, %1, %2;" : "=l"(d) : "l"(a), "l"(b));
    return d;
}
// fast exp via exp2 polynomial on the FMA pipe (MUFU is slow on B300)
__device__ __forceinline__ float expp(float x) {
    float y = fmaxf(x * 1.4426950408889634f, -120.f);
    float t = y + 12582912.f;
    int   e = __float_as_int(t);
    float r = t - 12582912.f;
    float f = y - r;
    float p = 1.3333558146e-3f;
    p = fmaf(p, f, 9.6181291076e-3f);
    p = fmaf(p, f, 5.5504108664e-2f);
    p = fmaf(p, f, 2.4022650696e-1f);
    p = fmaf(p, f, 6.9314718056e-1f);
    p = fmaf(p, f, 1.0f);
    float sc = __int_as_float((e - 0x4b400000 + 127) << 23);
    return p * sc;
}
// packed variant: identical per-lane IEEE-rn fp32 math, Horner on FFMA2.
__device__ __forceinline__ void expp2(float& xa, float& xb) {
    float ya = fmaxf(xa * 1.4426950408889634f, -120.f);
    float yb = fmaxf(xb * 1.4426950408889634f, -120.f);
    float ta = ya + 12582912.f;
    float tb = yb + 12582912.f;
    int ea = __float_as_int(ta);
    int eb = __float_as_int(tb);
    float fa = ya - (ta - 12582912.f);
    float fb = yb - (tb - 12582912.f);
    uint64_t f2 = pk2(fa, fb);
    uint64_t p2 = pk2(1.3333558146e-3f, 1.3333558146e-3f);
    p2 = fma2(p2, f2, pk2(9.6181291076e-3f, 9.6181291076e-3f));
    p2 = fma2(p2, f2, pk2(5.5504108664e-2f, 5.5504108664e-2f));
    p2 = fma2(p2, f2, pk2(2.4022650696e-1f, 2.4022650696e-1f));
    p2 = fma2(p2, f2, pk2(6.9314718056e-1f, 6.9314718056e-1f));
    p2 = fma2(p2, f2, pk2(1.0f, 1.0f));
    float pa, pb;
    upk2(p2, pa, pb);
    xa = pa * __int_as_float((ea - 0x4b400000 + 127) << 23);
    xb = pb * __int_as_float((eb - 0x4b400000 + 127) << 23);
}

__device__ __forceinline__ void store_pair(float* C, size_t off, float v0, float v1) {
    *(float2*)(C + off) = make_float2(v0, v1);
}
__device__ __forceinline__ void store_pair(bf16* C, size_t off, float v0, float v1) {
    *(bf162*)(C + off) = __float22bfloat162_rn(make_float2(v0, v1));
}

// ---------------------------------------------------------------------------
// bf16 mma GEMM: C[M,N] = A[M,K] @ B[N,K]^T (+bias, relu, residual)
// 128x256 block tile, 128-half k-chunk (272B padded rows), 2-stage double
// buffer, 8 warps (2m x 4n), warp tile 64x64. ONE __syncthreads per k-chunk.
// Next-chunk cp.async DISTRIBUTED across the 8 kk iterations (3 segs/thread
// per kk) to avoid front-batched LSU bursts colliding with LDSM/HMMA issue.
// ---------------------------------------------------------------------------
#define BM 128
#define BN 256
#define KCH 128
#define RSTR 272                     // 256B data + 16B pad
#define STAGE_B ((BM+BN)*RSTR)       // 104448 bytes
#define GEMM_SMEM (2*STAGE_B + 512)  // 209408

template<typename TO, bool RELU, bool RES, bool GATHER, bool SCATTER>
__global__ __launch_bounds__(256, 1) void gemm_mma(
    const bf16* __restrict__ A, const bf16* __restrict__ Bm,
    const float* __restrict__ bias, const float* __restrict__ Res,
    TO* __restrict__ C, int Nld, int K,
    int rowsPerExpert, long long bExpStride, int biasExpStride,
    const int* __restrict__ tokIdx, const float* __restrict__ gate)
{
    extern __shared__ char smem[];
    const uint32_t sb0 = smem_u32(smem);
    int* stok = (int*)(smem + 2*STAGE_B);
    const int tid = threadIdx.x;
    const int wid = tid >> 5, lane = tid & 31;
    const int j8 = lane & 7, gi = lane >> 3;
    const int lr = lane >> 2, lc = lane & 3;
    const int row0 = blockIdx.y * BM, col0 = blockIdx.x * BN;
    const int expert = row0 / rowsPerExpert;
    const bf16* Bexp = Bm + (long long)expert * bExpStride;
    const float* bb  = bias + (long long)expert * biasExpStride;
    const int m0 = (wid & 1) * 64, n0 = (wid >> 1) * 64;

    const bf16* Abase = GATHER ? A : A + (size_t)row0 * K;
    const bf16* Bbase = Bexp + (size_t)col0 * K;

    if (GATHER || SCATTER) {
        int v = 0;
        if (tid < BM) {
            int t = tokIdx[row0 + tid];
            stok[tid] = t;
            v = (t >= 0);
        }
        if (!__syncthreads_or(v)) return;   // whole tile empty -> no effect
    }

    const int arow = j8 + (gi & 1) * 8;
    const int aoff = (gi >> 1) * 16;
    const int brow = j8 + (gi >> 1) * 8;
    const int boff = (gi & 1) * 16;

    float acc[4][8][4];
#pragma unroll
    for (int mt = 0; mt < 4; mt++)
#pragma unroll
        for (int t = 0; t < 8; t++)
#pragma unroll
            for (int q = 0; q < 4; q++) acc[mt][t][q] = 0.f;

    const int nch = K / KCH;

    // one 16B A-segment (q in [0,8))
    auto load_A_seg = [&](int s, int ch, int q) {
        const uint32_t sa = sb0 + (uint32_t)s * STAGE_B;
        int seg = tid + 256 * q;
        int r = seg >> 4, c = seg & 15;
        if (GATHER) {
            int t = stok[r];
            uint32_t sz = (t >= 0) ? 16u : 0u;
            const bf16* srcp = Abase + (size_t)(t >= 0 ? t : 0) * K + ch * KCH + c * 8;
            cp16z(sa + (uint32_t)(r * RSTR + c * 16), srcp, sz);
        } else {
            cp16(sa + (uint32_t)(r * RSTR + c * 16),
                 Abase + (size_t)r * K + ch * KCH + c * 8);
        }
    };
    // one 16B B-segment (q in [0,16))
    auto load_B_seg = [&](int s, int ch, int q) {
        const uint32_t sbm = sb0 + (uint32_t)s * STAGE_B + BM * RSTR;
        const bf16* Bcp = Bbase + ch * KCH;
        int seg = tid + 256 * q;
        int r = seg >> 4, c = seg & 15;
        cp16(sbm + (uint32_t)(r * RSTR + c * 16), Bcp + (size_t)r * K + c * 8);
    };

    // prologue: chunk 0 loaded as a full batch
    {
#pragma unroll
        for (int q = 0; q < 8; q++)  load_A_seg(0, 0, q);
#pragma unroll
        for (int q = 0; q < 16; q++) load_B_seg(0, 0, q);
        asm volatile("cp.async.commit_group;");
    }

    for (int i = 0; i < nch; i++) {
        asm volatile("cp.async.wait_group 0;");
        __syncthreads();
        const bool havenext = (i + 1 < nch);
        const int ns = (i + 1) & 1;
        const uint32_t sa  = sb0 + (uint32_t)(i & 1) * STAGE_B;
        const uint32_t sbm = sa + BM * RSTR;
#pragma unroll
        for (int kk = 0; kk < KCH/16; kk++) {
            // distribute next-chunk loads: 1 A-seg + 2 B-segs per kk
            if (havenext) {
                load_A_seg(ns, i + 1, kk);
                load_B_seg(ns, i + 1, 2 * kk);
                load_B_seg(ns, i + 1, 2 * kk + 1);
            }
            uint32_t af[4][4];
#pragma unroll
            for (int mt = 0; mt < 4; mt++)
                ldm_x4(af[mt], sa + (uint32_t)((m0 + mt * 16 + arow) * RSTR + kk * 32 + aoff));
#pragma unroll
            for (int nt = 0; nt < 4; nt++) {
                uint32_t bfr[4];
                ldm_x4(bfr, sbm + (uint32_t)((n0 + nt * 16 + brow) * RSTR + kk * 32 + boff));
#pragma unroll
                for (int mt = 0; mt < 4; mt++) {
                    mma_bf16(acc[mt][nt * 2 + 0], af[mt], bfr[0], bfr[1]);
                    mma_bf16(acc[mt][nt * 2 + 1], af[mt], bfr[2], bfr[3]);
                }
            }
        }
        asm volatile("cp.async.commit_group;");
    }

    // epilogue
#pragma unroll
    for (int mt = 0; mt < 4; mt++) {
        const int gr = row0 + m0 + mt * 16 + lr;
        int t0 = 0, t1 = 0;
        float g0 = 0.f, g1 = 0.f;
        if (SCATTER) {
            t0 = stok[m0 + mt * 16 + lr]; t1 = stok[m0 + mt * 16 + lr + 8];
            g0 = (t0 >= 0) ? gate[t0] : 0.f;
            g1 = (t1 >= 0) ? gate[t1] : 0.f;
        }
#pragma unroll
        for (int nt = 0; nt < 4; nt++) {
#pragma unroll
            for (int pr = 0; pr < 2; pr++) {
                const int gc = col0 + n0 + nt * 16 + pr * 8 + lc * 2;
                float* d = acc[mt][nt * 2 + pr];
                float b0 = bb[gc], b1 = bb[gc + 1];
                float v0 = d[0] + b0, v1 = d[1] + b1;
                float v2 = d[2] + b0, v3 = d[3] + b1;
                if (RELU) {
                    v0 = fmaxf(v0, 0.f); v1 = fmaxf(v1, 0.f);
                    v2 = fmaxf(v2, 0.f); v3 = fmaxf(v3, 0.f);
                }
                if (RES) {
                    float2 r0 = *(const float2*)(Res + (size_t)gr * Nld + gc);
                    float2 r1 = *(const float2*)(Res + (size_t)(gr + 8) * Nld + gc);
                    v0 += r0.x; v1 += r0.y; v2 += r1.x; v3 += r1.y;
                }
                if (SCATTER) {
                    if (t0 >= 0) {
                        float2 cur = *(float2*)((float*)C + (size_t)t0 * Nld + gc);
                        *(float2*)((float*)C + (size_t)t0 * Nld + gc) =
                            make_float2(cur.x + g0 * v0, cur.y + g0 * v1);
                    }
                    if (t1 >= 0) {
                        float2 cur = *(float2*)((float*)C + (size_t)t1 * Nld + gc);
                        *(float2*)((float*)C + (size_t)t1 * Nld + gc) =
                            make_float2(cur.x + g1 * v2, cur.y + g1 * v3);
                    }
                } else {
                    store_pair(C, (size_t)gr * Nld + gc, v0, v1);
                    store_pair(C, (size_t)(gr + 8) * Nld + gc, v2, v3);
                }
            }
        }
    }
}

// ---------------------------------------------------------------------------
// Flash attention, bf16 mma. 256 threads (8 warps), q-tile 128, k-tiles of 64.
// ONE __syncthreads per k-tile. Fully-packed f32x2 softmax; rescale skipped
// (bit-identically) when the running max is unchanged warp-wide.
// ---------------------------------------------------------------------------
#define AT_SMEM (18432 + 9216*4 + 512)

__global__ __launch_bounds__(256, 2) void attn_mma(
    const bf16* __restrict__ qkv,
    const unsigned char* __restrict__ pad,
    bf16* __restrict__ outp)
{
    extern __shared__ char smem[];
    const uint32_t sQ  = smem_u32(smem);
    const uint32_t sK0 = sQ + 18432;
    const uint32_t sV0 = sK0 + 9216 * 2;
    float* mkp = (float*)(smem + 18432 + 9216 * 4);

    const int tid = threadIdx.x;
    const int wid = tid >> 5, lane = tid & 31;
    const int j8 = lane & 7, gi = lane >> 3;
    const int lc = lane & 3, lr = lane >> 2;
    const int bh = blockIdx.y, b = bh >> 4, h = bh & 15;
    const int q0 = blockIdx.x * 128;
    const size_t tokBase = (size_t)b * Sq;

    {
        const bf16* qb = qkv + (tokBase + q0) * 3072 + h * 64;
#pragma unroll
        for (int q = 0; q < 4; q++) {
            int seg = tid + 256 * q;
            int r = seg >> 3, c = seg & 7;
            cp16(sQ + (uint32_t)(r * 144 + c * 16), qb + (size_t)r * 3072 + c * 8);
        }
    }
    asm volatile("cp.async.commit_group;");

    auto prefetch = [&](int st, int kt) {
        const int k0 = kt * 64;
        const bf16* kb = qkv + (tokBase + k0) * 3072 + 1024 + h * 64;
        const bf16* vb = qkv + (tokBase + k0) * 3072 + 2048 + h * 64;
        const uint32_t sk = sK0 + (uint32_t)st * 9216, sv = sV0 + (uint32_t)st * 9216;
#pragma unroll
        for (int q = 0; q < 2; q++) {
            int seg = tid + 256 * q;
            int r = seg >> 3, c = seg & 7;
            cp16(sk + (uint32_t)(r * 144 + c * 16), kb + (size_t)r * 3072 + c * 8);
            cp16(sv + (uint32_t)(r * 144 + c * 16), vb + (size_t)r * 3072 + c * 8);
        }
        if (tid < 64) mkp[st * 64 + tid] = pad[tokBase + k0 + tid] ? -1e9f : 0.f;
    };

    prefetch(0, 0);
    asm volatile("cp.async.commit_group;");
    asm volatile("cp.async.wait_group 1;");
    __syncthreads();

    const int arow = j8 + (gi & 1) * 8, aoff = (gi >> 1) * 16;
    const int brow = j8 + (gi >> 1) * 8, boff = (gi & 1) * 16;

    uint32_t qa[4][4];
#pragma unroll
    for (int kd = 0; kd < 4; kd++)
        ldm_x4(qa[kd], sQ + (uint32_t)((wid * 16 + arow) * 144 + kd * 32 + aoff));

    float m0v = -1e30f, m1v = -1e30f, l0 = 0.f, l1 = 0.f;
    float o[8][4];
#pragma unroll
    for (int dt = 0; dt < 8; dt++)
#pragma unroll
        for (int q = 0; q < 4; q++) o[dt][q] = 0.f;

    const uint64_t scale2 = pk2(0.125f, 0.125f);

    for (int kt = 0; kt < Sq / 64; kt++) {
        const int st = kt & 1;
        asm volatile("cp.async.wait_group 0;");
        __syncthreads();
        if (kt + 1 < Sq / 64) prefetch(st ^ 1, kt + 1);
        asm volatile("cp.async.commit_group;");

        const uint32_t sk = sK0 + (uint32_t)st * 9216, sv = sV0 + (uint32_t)st * 9216;
        float s[8][4];
#pragma unroll
        for (int j = 0; j < 8; j++)
#pragma unroll
            for (int q = 0; q < 4; q++) s[j][q] = 0.f;

#pragma unroll
        for (int jp = 0; jp < 4; jp++) {
#pragma unroll
            for (int kd = 0; kd < 4; kd++) {
                uint32_t bfr[4];
                ldm_x4(bfr, sk + (uint32_t)((jp * 16 + brow) * 144 + kd * 32 + boff));
                mma_bf16(s[2 * jp],     qa[kd], bfr[0], bfr[1]);
                mma_bf16(s[2 * jp + 1], qa[kd], bfr[2], bfr[3]);
            }
        }

        // packed scale+mask, then row max
        float rmax0 = -1e30f, rmax1 = -1e30f;
#pragma unroll
        for (int j = 0; j < 8; j++) {
            const uint64_t mk2 = pk2(mkp[st * 64 + j * 8 + 2 * lc],
                                     mkp[st * 64 + j * 8 + 2 * lc + 1]);
            uint64_t v01 = fma2(pk2(s[j][0], s[j][1]), scale2, mk2);
            uint64_t v23 = fma2(pk2(s[j][2], s[j][3]), scale2, mk2);
            upk2(v01, s[j][0], s[j][1]);
            upk2(v23, s[j][2], s[j][3]);
            rmax0 = fmaxf(rmax0, fmaxf(s[j][0], s[j][1]));
            rmax1 = fmaxf(rmax1, fmaxf(s[j][2], s[j][3]));
        }
        rmax0 = fmaxf(rmax0, __shfl_xor_sync(0xffffffffu, rmax0, 1));
        rmax0 = fmaxf(rmax0, __shfl_xor_sync(0xffffffffu, rmax0, 2));
        rmax1 = fmaxf(rmax1, __shfl_xor_sync(0xffffffffu, rmax1, 1));
        rmax1 = fmaxf(rmax1, __shfl_xor_sync(0xffffffffu, rmax1, 2));
        float nm0 = fmaxf(m0v, rmax0), nm1 = fmaxf(m1v, rmax1);
        // exact: if neither row max moved, c0 == c1 == 1.0f -> skip rescale
        bool upd = (nm0 > m0v) || (nm1 > m1v);
        bool anyupd = __any_sync(0xffffffffu, upd);
        float c0 = 1.f, c1 = 1.f;
        if (anyupd) {
            c0 = m0v - nm0; c1 = m1v - nm1;
            expp2(c0, c1);
        }
        m0v = nm0; m1v = nm1;
        float rs0 = 0.f, rs1 = 0.f;
#pragma unroll
        for (int j = 0; j < 8; j++) {
            float a0 = s[j][0] - nm0, a1 = s[j][1] - nm0;
            float a2 = s[j][2] - nm1, a3 = s[j][3] - nm1;
            expp2(a0, a1);
            expp2(a2, a3);
            s[j][0] = a0; s[j][1] = a1; s[j][2] = a2; s[j][3] = a3;
            rs0 += a0 + a1;
            rs1 += a2 + a3;
        }
        rs0 += __shfl_xor_sync(0xffffffffu, rs0, 1);
        rs0 += __shfl_xor_sync(0xffffffffu, rs0, 2);
        rs1 += __shfl_xor_sync(0xffffffffu, rs1, 1);
        rs1 += __shfl_xor_sync(0xffffffffu, rs1, 2);
        if (anyupd) {
            l0 = fmaf(l0, c0, rs0); l1 = fmaf(l1, c1, rs1);
            const uint64_t c02 = pk2(c0, c0), c12 = pk2(c1, c1);
#pragma unroll
            for (int dt = 0; dt < 8; dt++) {
                uint64_t p01 = mul2(pk2(o[dt][0], o[dt][1]), c02);
                uint64_t p23 = mul2(pk2(o[dt][2], o[dt][3]), c12);
                upk2(p01, o[dt][0], o[dt][1]);
                upk2(p23, o[dt][2], o[dt][3]);
            }
        } else {
            l0 += rs0; l1 += rs1;
        }

        uint32_t pa[4][4];
#pragma unroll
        for (int t = 0; t < 4; t++) {
            pa[t][0] = pack_bf(s[2 * t][0],     s[2 * t][1]);
            pa[t][1] = pack_bf(s[2 * t][2],     s[2 * t][3]);
            pa[t][2] = pack_bf(s[2 * t + 1][0], s[2 * t + 1][1]);
            pa[t][3] = pack_bf(s[2 * t + 1][2], s[2 * t + 1][3]);
        }
#pragma unroll
        for (int t = 0; t < 4; t++) {
#pragma unroll
            for (int dp = 0; dp < 4; dp++) {
                uint32_t vf[4];
                ldm_x4t(vf, sv + (uint32_t)((t * 16 + arow) * 144 + dp * 32 + aoff));
                mma_bf16(o[2 * dp],     pa[t], vf[0], vf[1]);
                mma_bf16(o[2 * dp + 1], pa[t], vf[2], vf[3]);
            }
        }
    }

    float inv0 = 1.f / l0, inv1 = 1.f / l1;
    const int rg = q0 + wid * 16 + lr;
    bf16* ob = outp + (tokBase + rg) * Dm + h * 64;
#pragma unroll
    for (int dt = 0; dt < 8; dt++) {
        *(bf162*)(ob + dt * 8 + 2 * lc) =
            __float22bfloat162_rn(make_float2(o[dt][0] * inv0, o[dt][1] * inv0));
        *(bf162*)(ob + (size_t)8 * Dm + dt * 8 + 2 * lc) =
            __float22bfloat162_rn(make_float2(o[dt][2] * inv1, o[dt][3] * inv1));
    }
}

// ---------------------------------------------------------------------------
// LayerNorm (bf16 out, for LN1)
// ---------------------------------------------------------------------------
__global__ __launch_bounds__(256) void ln_kernel(const float* __restrict__ in,
                                                 const float* __restrict__ g,
                                                 const float* __restrict__ b,
                                                 bf16* __restrict__ out)
{
    int n = blockIdx.x, tid = threadIdx.x;
    float4 v = ((const float4*)(in + (size_t)n*Dm))[tid];
    float s  = v.x+v.y+v.z+v.w;
    float s2 = v.x*v.x+v.y*v.y+v.z*v.z+v.w*v.w;
    __shared__ float r1[256], r2[256];
    r1[tid]=s; r2[tid]=s2; __syncthreads();
    for (int st=128; st; st>>=1) {
        if (tid<st) { r1[tid]+=r1[tid+st]; r2[tid]+=r2[tid+st]; }
        __syncthreads();
    }
    float mean = r1[0]*(1.0f/Dm);
    float var  = r2[0]*(1.0f/Dm) - mean*mean;
    float rstd = rsqrtf(var + 1e-5f);
    float4 gg = ((const float4*)g)[tid];
    float4 bb = ((const float4*)b)[tid];
    float o0 = (v.x-mean)*rstd*gg.x + bb.x;
    float o1 = (v.y-mean)*rstd*gg.y + bb.y;
    float o2 = (v.z-mean)*rstd*gg.z + bb.z;
    float o3 = (v.w-mean)*rstd*gg.w + bb.w;
    size_t base = (size_t)n*Dm + tid*4;
    store_pair(out, base, o0, o1);
    store_pair(out, base + 2, o2, o3);
}

// ---------------------------------------------------------------------------
// LN2 + router fused (reads src1 values from `out` buffer)
// ---------------------------------------------------------------------------
__global__ __launch_bounds__(256) void ln2_router(const float* __restrict__ in,
                                                  const float* __restrict__ g,
                                                  const float* __restrict__ b,
                                                  bf16* __restrict__ outh,
                                                  const float* __restrict__ rw,
                                                  const float* __restrict__ rb,
                                                  const unsigned char* __restrict__ pad)
{
    int n = blockIdx.x, tid = threadIdx.x;
    __shared__ float r1[256], r2[256];
    __shared__ float xs[1024];
    __shared__ float lg[8];
    float4 v = ((const float4*)(in + (size_t)n*Dm))[tid];
    float s  = v.x+v.y+v.z+v.w;
    float s2 = v.x*v.x+v.y*v.y+v.z*v.z+v.w*v.w;
    r1[tid]=s; r2[tid]=s2; __syncthreads();
    for (int st=128; st; st>>=1) {
        if (tid<st) { r1[tid]+=r1[tid+st]; r2[tid]+=r2[tid+st]; }
        __syncthreads();
    }
    float mean = r1[0]*(1.0f/Dm);
    float var  = r2[0]*(1.0f/Dm) - mean*mean;
    float rstd = rsqrtf(var + 1e-5f);
    float4 gg = ((const float4*)g)[tid];
    float4 bb = ((const float4*)b)[tid];
    float4 o;
    o.x = (v.x-mean)*rstd*gg.x + bb.x;
    o.y = (v.y-mean)*rstd*gg.y + bb.y;
    o.z = (v.z-mean)*rstd*gg.z + bb.z;
    o.w = (v.w-mean)*rstd*gg.w + bb.w;
    bf162* hp = (bf162*)(outh + (size_t)n*Dm);
    hp[tid*2]   = __float22bfloat162_rn(make_float2(o.x, o.y));
    hp[tid*2+1] = __float22bfloat162_rn(make_float2(o.z, o.w));
    ((float4*)xs)[tid] = o;
    __syncthreads();
    int w = tid >> 5, lane = tid & 31;
    float acc = 0.f;
    for (int i = lane; i < 1024; i += 32) acc += xs[i] * rw[i*8 + w];
    for (int off=16; off; off>>=1) acc += __shfl_xor_sync(0xffffffffu, acc, off);
    if (lane == 0) lg[w] = acc + rb[w];
    __syncthreads();
    if (tid == 0) {
        float mx = lg[0]; int ei = 0;
        for (int e=1;e<8;e++) if (lg[e] > mx) { mx = lg[e]; ei = e; }
        float pr[8], se = 0.f;
        for (int e=0;e<8;e++) { pr[e] = expf(lg[e]-mx); se += pr[e]; }
        float inv = 1.f/se;
        bool valid = (pad[n] == 0);
        float tm = valid ? 1.f : 0.f;
        for (int e=0;e<8;e++) g_probs[n*8+e] = pr[e]*inv*tm;
        g_gate[n] = pr[ei]*inv;
        g_eidx[n] = ei;
        float lse = mx + logf(se);
        g_zterm[n] = lse*lse*tm;
    }
}

// ---------------------------------------------------------------------------
// Weight prep
// ---------------------------------------------------------------------------
__global__ __launch_bounds__(256) void bf16_copy(const float* __restrict__ in,
                                                 bf16* __restrict__ out, int n4)
{
    int i = blockIdx.x*256 + threadIdx.x;
    if (i < n4) {
        float4 v = ((const float4*)in)[i];
        ((bf162*)out)[i*2]   = __float22bfloat162_rn(make_float2(v.x, v.y));
        ((bf162*)out)[i*2+1] = __float22bfloat162_rn(make_float2(v.z, v.w));
    }
}

__global__ __launch_bounds__(256) void transpose_bf16(const float* __restrict__ in,
                                                      bf16* __restrict__ out,
                                                      int R, int Cc)
{
    __shared__ float t[32][33];
    int e = blockIdx.z;
    const float* ip = in  + (size_t)e*R*Cc;
    bf16* op        = out + (size_t)e*R*Cc;
    int c0 = blockIdx.x*32, r0 = blockIdx.y*32;
    int tx = threadIdx.x, ty = threadIdx.y;
#pragma unroll
    for (int j=0;j<32;j+=8)
        t[ty+j][tx] = ip[(size_t)(r0+ty+j)*Cc + c0+tx];
    __syncthreads();
#pragma unroll
    for (int j=0;j<32;j+=8)
        op[(size_t)(c0+ty+j)*R + r0+tx] = __float2bfloat16_rn(t[tx][ty+j]);
}

// ---------------------------------------------------------------------------
// Routing scan
// ---------------------------------------------------------------------------
__global__ __launch_bounds__(1024) void scan_kernel(const unsigned char* __restrict__ pad)
{
    __shared__ unsigned char sc[Ntok];
    __shared__ int base[8];
    int tid = threadIdx.x;
    for (int i = tid; i < SLOTS; i += 1024) g_tok[i] = -1;
    for (int i = tid; i < Ntok; i += 1024)
        sc[i] = (unsigned char)(g_eidx[i] | (pad[i] ? 0 : 16));
    if (tid < 8) base[tid] = 0;
    __syncthreads();
    if (tid < 32) {
        int lane = tid;
        for (int c = 0; c < Ntok/32; c++) {
            int i = c*32 + lane;
            int code = sc[i];
            int e = code & 7;
            bool valid = (code & 16) != 0;
            unsigned peers = __match_any_sync(0xffffffffu, e);
            unsigned vmask = __ballot_sync(0xffffffffu, valid);
            unsigned pv = peers & vmask;
            int myrank = __popc(pv & ((1u << lane) - 1u));
            int b0 = base[e];
            __syncwarp();
            int pos = b0 + myrank;
            bool keep = valid && (pos < CAP);
            if (keep) g_tok[e*CAP + pos] = i;
            if (valid && lane == (__ffs(pv) - 1)) base[e] = b0 + __popc(pv);
            __syncwarp();
        }
        if (lane < 8) g_cnt[lane] = base[lane];
    }
}

// ---------------------------------------------------------------------------
// Loss reduction
// ---------------------------------------------------------------------------
__global__ __launch_bounds__(256) void loss_kernel(const unsigned char* __restrict__ pad,
                                                   float* __restrict__ out)
{
    int tid = threadIdx.x;
    float zs = 0.f, ps[8];
    int cnt = 0;
#pragma unroll
    for (int e=0;e<8;e++) ps[e]=0.f;
    for (int n = tid; n < Ntok; n += 256) {
        if (pad[n] == 0) cnt++;
        zs += g_zterm[n];
#pragma unroll
        for (int e=0;e<8;e++) ps[e] += g_probs[n*8+e];
    }
    __shared__ float red[256];
    __shared__ float res[10];
    float vals[10];
    vals[0] = (float)cnt; vals[1] = zs;
    for (int e=0;e<8;e++) vals[2+e] = ps[e];
    for (int q=0;q<10;q++) {
        red[tid] = vals[q]; __syncthreads();
        for (int st=128; st; st>>=1) {
            if (tid < st) red[tid] += red[tid+st];
            __syncthreads();
        }
        if (tid == 0) res[q] = red[0];
        __syncthreads();
    }
    if (tid == 0) {
        float denom = fmaxf(res[0], 1.f);
        float lb = 0.f;
        for (int e=0;e<8;e++) lb += ((float)g_cnt[e]/denom) * (res[2+e]/denom);
        lb *= (float)Ee;
        out[(size_t)Ntok*Dm]     = lb;
        out[(size_t)Ntok*Dm + 1] = res[1]/denom;
    }
}

// ---------------------------------------------------------------------------
// Launch
// ---------------------------------------------------------------------------
extern "C" void kernel_launch(void* const* d_in, const int* in_sizes, int n_in,
                              void* d_out, int out_size)
{
    const float* src  = (const float*)d_in[0];
    const unsigned char* pad = (const unsigned char*)d_in[1];
    const float* ln1g = (const float*)d_in[2];
    const float* ln1b = (const float*)d_in[3];
    const float* ipw  = (const float*)d_in[4];
    const float* ipb  = (const float*)d_in[5];
    const float* opw  = (const float*)d_in[6];
    const float* opb  = (const float*)d_in[7];
    const float* ln2g = (const float*)d_in[8];
    const float* ln2b = (const float*)d_in[9];
    const float* rw   = (const float*)d_in[10];
    const float* rb   = (const float*)d_in[11];
    const float* w1   = (const float*)d_in[12];
    const float* b1   = (const float*)d_in[13];
    const float* w2   = (const float*)d_in[14];
    const float* b2   = (const float*)d_in[15];
    float* out = (float*)d_out;

    bf16 *xln, *qkv, *attn, *x2b, *hb, *ipw16, *opw16, *w1t, *w2t;
    float *gate;
    int *tok;
    cudaGetSymbolAddress((void**)&xln,  g_xln);
    cudaGetSymbolAddress((void**)&qkv,  g_qkv);
    cudaGetSymbolAddress((void**)&attn, g_attn);
    cudaGetSymbolAddress((void**)&x2b,  g_x2b);
    cudaGetSymbolAddress((void**)&hb,   g_hbuf);
    cudaGetSymbolAddress((void**)&ipw16, g_ipw16);
    cudaGetSymbolAddress((void**)&opw16, g_opw16);
    cudaGetSymbolAddress((void**)&w1t,  g_w1t);
    cudaGetSymbolAddress((void**)&w2t,  g_w2t);
    cudaGetSymbolAddress((void**)&tok,  g_tok);
    cudaGetSymbolAddress((void**)&gate, g_gate);

    static cudaStream_t s2 = nullptr;
    static cudaEvent_t ev0 = nullptr, evA = nullptr, ev1 = nullptr,
                       ev2 = nullptr, ev3 = nullptr;
    if (!s2) {
        cudaStreamCreateWithFlags(&s2, cudaStreamNonBlocking);
        cudaEventCreateWithFlags(&ev0, cudaEventDisableTiming);
        cudaEventCreateWithFlags(&evA, cudaEventDisableTiming);
        cudaEventCreateWithFlags(&ev1, cudaEventDisableTiming);
        cudaEventCreateWithFlags(&ev2, cudaEventDisableTiming);
        cudaEventCreateWithFlags(&ev3, cudaEventDisableTiming);
    }

    cudaFuncSetAttribute(attn_mma, cudaFuncAttributeMaxDynamicSharedMemorySize, AT_SMEM);
    cudaFuncSetAttribute(gemm_mma<bf16,false,false,false,false>, cudaFuncAttributeMaxDynamicSharedMemorySize, GEMM_SMEM);
    cudaFuncSetAttribute(gemm_mma<float,false,true,false,false>, cudaFuncAttributeMaxDynamicSharedMemorySize, GEMM_SMEM);
    cudaFuncSetAttribute(gemm_mma<bf16,true,false,true,false>,   cudaFuncAttributeMaxDynamicSharedMemorySize, GEMM_SMEM);
    cudaFuncSetAttribute(gemm_mma<float,false,false,false,true>, cudaFuncAttributeMaxDynamicSharedMemorySize, GEMM_SMEM);

    // Fork: ALL weight prep on side stream. ipw16 first (QKV gates on evA).
    cudaEventRecord(ev0, 0);
    cudaStreamWaitEvent(s2, ev0, 0);
    bf16_copy<<<(3*Dm*Dm/4 + 255)/256, 256, 0, s2>>>(ipw, ipw16, 3*Dm*Dm/4);
    cudaEventRecord(evA, s2);
    bf16_copy<<<(Dm*Dm/4 + 255)/256, 256, 0, s2>>>(opw, opw16, Dm*Dm/4);
    transpose_bf16<<<dim3(Ff/32, Dm/32, Ee), dim3(32,8), 0, s2>>>(w1, w1t, Dm, Ff);
    transpose_bf16<<<dim3(Dm/32, Ff/32, Ee), dim3(32,8), 0, s2>>>(w2, w2t, Ff, Dm);
    cudaEventRecord(ev1, s2);

    // Main stream: LN1 overlaps ipw copy.
    ln_kernel<<<Ntok, 256>>>(src, ln1g, ln1b, xln);
    cudaStreamWaitEvent(0, evA, 0);
    // 2. QKV -> bf16
    gemm_mma<bf16,false,false,false,false><<<dim3(3072/BN, Ntok/BM), 256, GEMM_SMEM>>>(
        xln, ipw16, ipb, nullptr, qkv, 3072, 1024, 1<<30, 0, 0, nullptr, nullptr);
    // 3. Attention -> bf16
    attn_mma<<<dim3(Sq/128, Bc*Hh), 256, AT_SMEM>>>(qkv, pad, attn);
    cudaStreamWaitEvent(0, ev1, 0);
    // 4. out_proj + residual(src) -> out directly
    gemm_mma<float,false,true,false,false><<<dim3(1024/BN, Ntok/BM), 256, GEMM_SMEM>>>(
        attn, opw16, opb, src, out, 1024, 1024, 1<<30, 0, 0, nullptr, nullptr);
    // 5. LN2 + router fused (reads src1 values from out)
    ln2_router<<<Ntok, 256>>>(out, ln2g, ln2b, x2b, rw, rb, pad);
    // 6. Scan
    scan_kernel<<<1, 1024>>>(pad);
    // Fork: loss on side stream.
    cudaEventRecord(ev2, 0);
    cudaStreamWaitEvent(s2, ev2, 0);
    loss_kernel<<<1, 256, 0, s2>>>(pad, out);
    cudaEventRecord(ev3, s2);
    // 7. FFN1 (gather, relu, empty-tile skip)
    gemm_mma<bf16,true,false,true,false><<<dim3(Ff/BN, SLOTS/BM), 256, GEMM_SMEM>>>(
        x2b, w1t, b1, nullptr, hb, Ff, 1024, CAP, (long long)Dm*Ff, Ff, tok, nullptr);
    // 8. FFN2 (scatter-add into out with gate, empty-tile skip)
    gemm_mma<float,false,false,false,true><<<dim3(Dm/BN, SLOTS/BM), 256, GEMM_SMEM>>>(
        hb, w2t, b2, nullptr, out, 1024, Ff, CAP, (long long)Ff*Dm, Dm, tok, gate);
    cudaStreamWaitEvent(0, ev3, 0);
}